// round 1
// baseline (speedup 1.0000x reference)
#include <cuda_runtime.h>
#include <math.h>
#include <float.h>

#define NN 20000
#define EE 320000
#define MM 3
#define FIN 128
#define HH 4
#define CC 64
#define NEG_SLOPE 0.2f

// ---------------- scratch (device globals; no allocation allowed) ----------------
__device__ float    g_h[NN * HH * CC];      // projected features (layer1: N*4*64, layer2 uses first N*64)
__device__ float    g_agg[NN * HH * CC];    // aggregation accumulator
__device__ float    g_asrc[NN * HH];
__device__ float    g_adst[NN * HH];
__device__ unsigned g_amax[NN * HH];        // monotonic-encoded float max
__device__ float    g_denom[NN * HH];
__device__ float    g_ex[EE * HH];          // alpha, then exp(alpha-max) in place
__device__ float    g_zstack[NN * MM * CC]; // per-metapath outputs
__device__ float    g_hout[NN * CC];        // layer-1 semantic-fused output
__device__ float    g_stats[4];             // sum, sumsq, bn_scale, bn_shift
__device__ float    g_edot[HH];             // per-head edge-attention scalar

// ---------------- helpers ----------------
__device__ __forceinline__ unsigned fenc(float f) {
    unsigned u = __float_as_uint(f);
    return (u & 0x80000000u) ? ~u : (u | 0x80000000u);
}
__device__ __forceinline__ float fdec(unsigned u) {
    return (u & 0x80000000u) ? __uint_as_float(u & 0x7fffffffu)
                             : __uint_as_float(~u);
}
__device__ __forceinline__ void red_add_v4(float* addr, float a, float b, float c, float d) {
    asm volatile("red.global.add.v4.f32 [%0], {%1,%2,%3,%4};"
                 :: "l"(addr), "f"(a), "f"(b), "f"(c), "f"(d) : "memory");
}
__device__ __forceinline__ float elu1(float x) { return x > 0.f ? x : expm1f(x); }

// ---------------- kernels ----------------

// zero agg / denom / stats, set amax = enc(-FLT_MAX)
__global__ void k_init(int total, int nh) {
    int i = blockIdx.x * blockDim.x + threadIdx.x;
    if (i < total) g_agg[i] = 0.f;
    if (i < nh) { g_amax[i] = fenc(-FLT_MAX); g_denom[i] = 0.f; }
    if (i < 2) g_stats[i] = 0.f;
}

// BN statistics of log1p(edge_attr): sum and sum-of-squares
__global__ void k_bnstats(const float* __restrict__ attr) {
    int i = blockIdx.x * blockDim.x + threadIdx.x;
    float v = 0.f, v2 = 0.f;
    if (i < EE) { float t = log1pf(attr[i]); v = t; v2 = t * t; }
#pragma unroll
    for (int o = 16; o; o >>= 1) {
        v  += __shfl_down_sync(0xffffffffu, v,  o);
        v2 += __shfl_down_sync(0xffffffffu, v2, o);
    }
    __shared__ float s1[8], s2[8];
    int lane = threadIdx.x & 31, w = threadIdx.x >> 5;
    if (lane == 0) { s1[w] = v; s2[w] = v2; }
    __syncthreads();
    if (threadIdx.x == 0) {
        float a = 0.f, b = 0.f;
        for (int j = 0; j < 8; j++) { a += s1[j]; b += s2[j]; }
        atomicAdd(&g_stats[0], a);
        atomicAdd(&g_stats[1], b);
    }
}

// finalize BN affine (scale/shift) and per-head edge-attention scalar edot[h]
template<int H, int C>
__global__ void k_bnfin(const float* __restrict__ lew, const float* __restrict__ aew,
                        const float* __restrict__ gamma, const float* __restrict__ beta) {
    __shared__ float sh[H * C];
    int t = threadIdx.x;            // H*C threads
    sh[t] = lew[t] * aew[t];
    __syncthreads();
    if ((t & (C - 1)) == 0) {
        float s = 0.f;
        for (int j = 0; j < C; j++) s += sh[t + j];
        g_edot[t / C] = s;
    }
    if (t == 0) {
        float mu   = g_stats[0] * (1.f / EE);
        float var  = g_stats[1] * (1.f / EE) - mu * mu;
        float istd = rsqrtf(var + 1e-5f);
        float sc   = gamma[0] * istd;
        g_stats[2] = sc;
        g_stats[3] = beta[0] - mu * sc;
    }
}

// h = x @ W, fused per-head a_src / a_dst reductions. one block per node, H*C threads
template<int F, int H, int C>
__global__ void k_gemm(const float* __restrict__ x, const float* __restrict__ W,
                       const float* __restrict__ asw, const float* __restrict__ adw) {
    constexpr int HC = H * C;
    __shared__ float xs[F];
    __shared__ float ps[HC], pd[HC];
    int n = blockIdx.x;
    int o = threadIdx.x;
    for (int k = o; k < F; k += HC) xs[k] = x[n * F + k];
    __syncthreads();
    float acc = 0.f;
#pragma unroll 16
    for (int k = 0; k < F; k++) acc += xs[k] * W[k * HC + o];
    g_h[n * HC + o] = acc;
    ps[o] = acc * asw[o];
    pd[o] = acc * adw[o];
    __syncthreads();
    if ((o & (C - 1)) == 0) {
        float s = 0.f, d = 0.f;
        for (int j = 0; j < C; j++) { s += ps[o + j]; d += pd[o + j]; }
        int head = o / C;
        g_asrc[n * H + head] = s;
        g_adst[n * H + head] = d;
    }
}

// alpha = leaky_relu(a_src[src] + a_dst[dst] + ea*edot), segment max via atomicMax
template<int H>
__global__ void k_edge_alpha(const int* __restrict__ ei, const float* __restrict__ attr) {
    int e = blockIdx.x * blockDim.x + threadIdx.x;
    if (e >= EE) return;
    int s = ei[e], d = ei[EE + e];
    float ea = log1pf(attr[e]) * g_stats[2] + g_stats[3];
#pragma unroll
    for (int h = 0; h < H; h++) {
        float a = g_asrc[s * H + h] + g_adst[d * H + h] + ea * g_edot[h];
        a = a > 0.f ? a : NEG_SLOPE * a;
        g_ex[e * H + h] = a;
        atomicMax(&g_amax[d * H + h], fenc(a));
    }
}

// ex = exp(alpha - max), denom accumulate
template<int H>
__global__ void k_edge_exp(const int* __restrict__ ei) {
    int idx = blockIdx.x * blockDim.x + threadIdx.x;
    if (idx >= EE * H) return;
    int e = idx / H, h = idx - e * H;
    int d = ei[EE + e];
    float ex = expf(g_ex[idx] - fdec(g_amax[d * H + h]));
    g_ex[idx] = ex;
    atomicAdd(&g_denom[d * H + h], ex);
}

// agg[dst] += h[src] * (ex/denom), vectorized float4 reductions
template<int H, int C>
__global__ void k_edge_agg(const int* __restrict__ ei) {
    constexpr int HC = H * C;
    constexpr int CH4 = HC / 4;
    int idx = blockIdx.x * blockDim.x + threadIdx.x;
    if (idx >= EE * CH4) return;
    int e = idx / CH4, q = idx - e * CH4;
    int s = ei[e], d = ei[EE + e];
    int h = (4 * q) / C;
    float w = g_ex[e * H + h] / (g_denom[d * H + h] + 1e-16f);
    const float4 hv = *(const float4*)(g_h + s * HC + 4 * q);
    red_add_v4(g_agg + d * HC + 4 * q, hv.x * w, hv.y * w, hv.z * w, hv.w * w);
}

// z_stack[:,m,:] = elu(mean_h(agg) + bias)
template<int H, int C>
__global__ void k_node_fin(const float* __restrict__ bias, int m) {
    int idx = blockIdx.x * blockDim.x + threadIdx.x;
    if (idx >= NN * C) return;
    int n = idx / C, c = idx - n * C;
    float s = 0.f;
#pragma unroll
    for (int h = 0; h < H; h++) s += g_agg[n * H * C + h * C + c];
    s = s * (1.f / H) + bias[c];
    g_zstack[n * MM * C + m * C + c] = elu1(s);
}

// semantic attention: per node, score_m = sum_c tanh(z_m @ W + b)_c * v_c; softmax over M
__global__ void k_semantic(const float* __restrict__ semw, const float* __restrict__ semb,
                           const float* __restrict__ semv,
                           float* __restrict__ out, float* beta_out) {
    __shared__ float zs[MM][CC];
    __shared__ float red[CC];
    __shared__ float sc[MM];
    int n = blockIdx.x, c = threadIdx.x;    // 64 threads
#pragma unroll
    for (int m = 0; m < MM; m++) zs[m][c] = g_zstack[n * MM * CC + m * CC + c];
    __syncthreads();
#pragma unroll
    for (int m = 0; m < MM; m++) {
        float acc = semb[c];
#pragma unroll 16
        for (int k = 0; k < CC; k++) acc += zs[m][k] * semw[k * CC + c];
        red[c] = tanhf(acc) * semv[c];
        __syncthreads();
        for (int s = 32; s; s >>= 1) {
            if (c < s) red[c] += red[c + s];
            __syncthreads();
        }
        if (c == 0) sc[m] = red[0];
        __syncthreads();
    }
    if (c == 0) {
        float mx = fmaxf(sc[0], fmaxf(sc[1], sc[2]));
        float e0 = expf(sc[0] - mx), e1 = expf(sc[1] - mx), e2 = expf(sc[2] - mx);
        float inv = 1.f / (e0 + e1 + e2);
        sc[0] = e0 * inv; sc[1] = e1 * inv; sc[2] = e2 * inv;
    }
    __syncthreads();
    out[n * CC + c] = zs[0][c] * sc[0] + zs[1][c] * sc[1] + zs[2][c] * sc[2];
    if (beta_out != nullptr && c < MM) beta_out[n * MM + c] = sc[c];
}

// fused 2-layer decoder: x_hat = elu(z@W1 + b1) @ W2 + b2
__global__ void k_decoder(const float* __restrict__ z,
                          const float* __restrict__ w1, const float* __restrict__ b1,
                          const float* __restrict__ w2, const float* __restrict__ b2,
                          float* __restrict__ xhat) {
    __shared__ float zsh[CC], tsh[CC];
    int n = blockIdx.x, t = threadIdx.x;    // 128 threads
    if (t < CC) zsh[t] = z[n * CC + t];
    __syncthreads();
    if (t < CC) {
        float acc = b1[t];
#pragma unroll 16
        for (int k = 0; k < CC; k++) acc += zsh[k] * w1[k * CC + t];
        tsh[t] = elu1(acc);
    }
    __syncthreads();
    float acc = b2[t];
#pragma unroll 16
    for (int k = 0; k < CC; k++) acc += tsh[k] * w2[k * FIN + t];
    xhat[n * FIN + t] = acc;
}

// ---------------- host-side metapath pipeline ----------------
template<int F, int H, int C>
static void run_gat(const float* x, const int* ei, const float* attr,
                    const float* linw, const float* asw, const float* adw,
                    const float* lew, const float* aew, const float* bias,
                    const float* bng, const float* bnb, int m) {
    constexpr int HC = H * C;
    k_init<<<(NN * HC + 255) / 256, 256>>>(NN * HC, NN * H);
    k_bnstats<<<(EE + 255) / 256, 256>>>(attr);
    k_bnfin<H, C><<<1, HC>>>(lew, aew, bng, bnb);
    k_gemm<F, H, C><<<NN, HC>>>(x, linw, asw, adw);
    k_edge_alpha<H><<<(EE + 255) / 256, 256>>>(ei, attr);
    k_edge_exp<H><<<(EE * H + 255) / 256, 256>>>(ei);
    k_edge_agg<H, C><<<(EE * (HC / 4) + 255) / 256, 256>>>(ei);
    k_node_fin<H, C><<<(NN * C + 255) / 256, 256>>>(bias, m);
}

extern "C" void kernel_launch(void* const* d_in, const int* in_sizes, int n_in,
                              void* d_out, int out_size) {
    const float* x      = (const float*)d_in[0];
    const int*   ei     = (const int*)  d_in[1];   // [M,2,E]
    const float* eattr  = (const float*)d_in[2];   // [M,E,1]
    const float* lin1w  = (const float*)d_in[3];
    const float* a1s    = (const float*)d_in[4];
    const float* a1d    = (const float*)d_in[5];
    const float* l1e    = (const float*)d_in[6];
    const float* a1e    = (const float*)d_in[7];
    const float* b1     = (const float*)d_in[8];
    const float* bn1g   = (const float*)d_in[9];
    const float* bn1b   = (const float*)d_in[10];
    const float* sem1w  = (const float*)d_in[11];
    const float* sem1b  = (const float*)d_in[12];
    const float* sem1v  = (const float*)d_in[13];
    const float* lin2w  = (const float*)d_in[14];
    const float* a2s    = (const float*)d_in[15];
    const float* a2d    = (const float*)d_in[16];
    const float* l2e    = (const float*)d_in[17];
    const float* a2e    = (const float*)d_in[18];
    const float* b2     = (const float*)d_in[19];
    const float* bn2g   = (const float*)d_in[20];
    const float* bn2b   = (const float*)d_in[21];
    const float* sem2w  = (const float*)d_in[22];
    const float* sem2b  = (const float*)d_in[23];
    const float* sem2v  = (const float*)d_in[24];
    const float* dec1w  = (const float*)d_in[25];
    const float* dec1b  = (const float*)d_in[26];
    const float* dec2w  = (const float*)d_in[27];
    const float* dec2b  = (const float*)d_in[28];

    float* z_out    = (float*)d_out;             // [N, C2]
    float* xhat     = z_out + NN * CC;           // [N, IN]
    float* beta_out = xhat + NN * FIN;           // [N, M]

    float* houtp = nullptr;
    cudaGetSymbolAddress((void**)&houtp, g_hout);

    // ---- HAN layer 1 (heads = 4) ----
    for (int m = 0; m < MM; m++) {
        run_gat<FIN, HH, CC>(x, ei + m * 2 * EE, eattr + m * EE,
                             lin1w + m * FIN * HH * CC,
                             a1s + m * HH * CC, a1d + m * HH * CC,
                             l1e + m * HH * CC, a1e + m * HH * CC,
                             b1 + m * CC, bn1g + m, bn1b + m, m);
    }
    k_semantic<<<NN, CC>>>(sem1w, sem1b, sem1v, houtp, nullptr);

    // ---- HAN layer 2 (heads = 1) ----
    for (int m = 0; m < MM; m++) {
        run_gat<CC, 1, CC>(houtp, ei + m * 2 * EE, eattr + m * EE,
                           lin2w + m * CC * CC,
                           a2s + m * CC, a2d + m * CC,
                           l2e + m * CC, a2e + m * CC,
                           b2 + m * CC, bn2g + m, bn2b + m, m);
    }
    k_semantic<<<NN, CC>>>(sem2w, sem2b, sem2v, z_out, beta_out);

    // ---- decoder ----
    k_decoder<<<NN, FIN>>>(z_out, dec1w, dec1b, dec2w, dec2b, xhat);
}

// round 2
// speedup vs baseline: 1.4785x; 1.4785x over previous
#include <cuda_runtime.h>
#include <math.h>
#include <float.h>

#define NN 20000
#define EE 320000
#define MM 3
#define FIN 128
#define HH 4
#define CC 64
#define NEG_SLOPE 0.2f

// ---------------- scratch (device globals; no allocation allowed) ----------------
__device__ __align__(16) float g_h[MM * NN * HH * CC];    // projected features per metapath
__device__ __align__(16) float g_agg[MM * NN * HH * CC];  // aggregation accumulators
__device__ __align__(16) float g_asrc[MM * NN * HH];
__device__ __align__(16) float g_adst[MM * NN * HH];
__device__ __align__(16) float g_denom[MM * NN * HH];
__device__ __align__(16) float g_ex[MM * EE * HH];        // exp(alpha), then normalized weight
__device__ __align__(16) float g_zstack[NN * MM * CC];
__device__ __align__(16) float g_hout[NN * CC];
__device__ float g_stats[MM * 4];                          // per m: sum, sumsq, scale, shift
__device__ float g_edot[MM * HH];

// ---------------- helpers ----------------
__device__ __forceinline__ void red_add_v4(float* addr, float a, float b, float c, float d) {
    asm volatile("red.global.add.v4.f32 [%0], {%1,%2,%3,%4};"
                 :: "l"(addr), "f"(a), "f"(b), "f"(c), "f"(d) : "memory");
}
__device__ __forceinline__ float elu1(float x) { return x > 0.f ? x : expm1f(x); }
__device__ __forceinline__ float lrelu_exp(float a) {
    a = a > 0.f ? a : NEG_SLOPE * a;
    return expf(a);
}

// ---------------- init: zero agg / denom (+stats once) ----------------
__global__ void k_init(int nagg4, int nden, int zstats) {
    int i = blockIdx.x * blockDim.x + threadIdx.x;
    if (i < nagg4) ((float4*)g_agg)[i] = make_float4(0.f, 0.f, 0.f, 0.f);
    if (i < nden) g_denom[i] = 0.f;
    if (zstats && i < MM * 4) g_stats[i] = 0.f;
}

// ---------------- BN statistics of log1p(edge_attr), all metapaths ----------------
__global__ void k_bnstats(const float* __restrict__ attr) {
    int m = blockIdx.y;
    int i = blockIdx.x * blockDim.x + threadIdx.x;
    float v = 0.f, v2 = 0.f;
    if (i < EE) { float t = log1pf(attr[m * EE + i]); v = t; v2 = t * t; }
#pragma unroll
    for (int o = 16; o; o >>= 1) {
        v  += __shfl_down_sync(0xffffffffu, v,  o);
        v2 += __shfl_down_sync(0xffffffffu, v2, o);
    }
    __shared__ float s1[8], s2[8];
    int lane = threadIdx.x & 31, w = threadIdx.x >> 5;
    if (lane == 0) { s1[w] = v; s2[w] = v2; }
    __syncthreads();
    if (threadIdx.x == 0) {
        float a = 0.f, b = 0.f;
        for (int j = 0; j < 8; j++) { a += s1[j]; b += s2[j]; }
        atomicAdd(&g_stats[m * 4 + 0], a);
        atomicAdd(&g_stats[m * 4 + 1], b);
    }
}

// ---------------- finalize BN affine + per-head edge scalar, all m ----------------
template<int H, int C>
__global__ void k_bnfin(const float* __restrict__ lew, const float* __restrict__ aew,
                        const float* __restrict__ gamma, const float* __restrict__ beta) {
    int w = threadIdx.x >> 5, lane = threadIdx.x & 31;   // MM*H warps
    int m = w / H, h = w % H;
    float s = 0.f;
    for (int c = lane; c < C; c += 32)
        s += lew[(m * H + h) * C + c] * aew[(m * H + h) * C + c];
#pragma unroll
    for (int o = 16; o; o >>= 1) s += __shfl_down_sync(0xffffffffu, s, o);
    if (lane == 0) g_edot[m * H + h] = s;
    if (threadIdx.x < MM) {
        int mm = threadIdx.x;
        float mu   = g_stats[mm * 4 + 0] * (1.f / EE);
        float var  = g_stats[mm * 4 + 1] * (1.f / EE) - mu * mu;
        float sc   = gamma[mm] * rsqrtf(var + 1e-5f);
        g_stats[mm * 4 + 2] = sc;
        g_stats[mm * 4 + 3] = beta[mm] - mu * sc;
    }
}

// ---------------- tiled SGEMM: g_h[m] = X @ W[m]   (64x64 tiles, 4x4 regblock) ----
template<int K, int NC>
__global__ void k_sgemm(const float* __restrict__ X, const float* __restrict__ Wall) {
    __shared__ float Xs[64][65];        // [node][k] padded
    __shared__ float Ws[64][64];        // [k][col]
    int m = blockIdx.z;
    const float* W = Wall + m * K * NC;
    float* Hd = g_h + (size_t)m * NN * NC;
    int nb = blockIdx.y * 64;
    int cb = blockIdx.x * 64;
    int tid = threadIdx.x;
    int tx = tid & 15, ty = tid >> 4;
    float acc[4][4] = {};
    for (int kt = 0; kt < K; kt += 64) {
        // X tile: 64 nodes x 64 k
#pragma unroll
        for (int i = 0; i < 4; i++) {
            int v = tid + i * 256;
            int row = v >> 4;
            int kq = (v & 15) << 2;
            int gr = nb + row;
            float4 xv = make_float4(0.f, 0.f, 0.f, 0.f);
            if (gr < NN) xv = *(const float4*)(X + gr * K + kt + kq);
            Xs[row][kq + 0] = xv.x; Xs[row][kq + 1] = xv.y;
            Xs[row][kq + 2] = xv.z; Xs[row][kq + 3] = xv.w;
        }
        // W tile: 64 k x 64 cols
#pragma unroll
        for (int i = 0; i < 4; i++) {
            int v = tid + i * 256;
            int k = v >> 4;
            int cq = (v & 15) << 2;
            *(float4*)&Ws[k][cq] = *(const float4*)(W + (kt + k) * NC + cb + cq);
        }
        __syncthreads();
#pragma unroll 16
        for (int k = 0; k < 64; k++) {
            float a0 = Xs[ty * 4 + 0][k];
            float a1 = Xs[ty * 4 + 1][k];
            float a2 = Xs[ty * 4 + 2][k];
            float a3 = Xs[ty * 4 + 3][k];
            float4 b = *(float4*)&Ws[k][tx * 4];
            acc[0][0] += a0 * b.x; acc[0][1] += a0 * b.y; acc[0][2] += a0 * b.z; acc[0][3] += a0 * b.w;
            acc[1][0] += a1 * b.x; acc[1][1] += a1 * b.y; acc[1][2] += a1 * b.z; acc[1][3] += a1 * b.w;
            acc[2][0] += a2 * b.x; acc[2][1] += a2 * b.y; acc[2][2] += a2 * b.z; acc[2][3] += a2 * b.w;
            acc[3][0] += a3 * b.x; acc[3][1] += a3 * b.y; acc[3][2] += a3 * b.z; acc[3][3] += a3 * b.w;
        }
        __syncthreads();
    }
#pragma unroll
    for (int i = 0; i < 4; i++) {
        int gr = nb + ty * 4 + i;
        if (gr < NN)
            *(float4*)(Hd + (size_t)gr * NC + cb + tx * 4) =
                make_float4(acc[i][0], acc[i][1], acc[i][2], acc[i][3]);
    }
}

// ---------------- per-node attention dots a_src/a_dst ----------------
template<int H, int C>
__global__ void k_attdot(const float* __restrict__ asw, const float* __restrict__ adw) {
    constexpr int HC = H * C;
    __shared__ float ps[HC], pd[HC];
    int n = blockIdx.x, m = blockIdx.y;
    int o = threadIdx.x;
    float v = g_h[(size_t)m * NN * HC + (size_t)n * HC + o];
    ps[o] = v * asw[m * HC + o];
    pd[o] = v * adw[m * HC + o];
    __syncthreads();
    if ((o & (C - 1)) == 0) {
        float s = 0.f, d = 0.f;
#pragma unroll 16
        for (int j = 0; j < C; j++) { s += ps[o + j]; d += pd[o + j]; }
        int h = o / C;
        g_asrc[(m * NN + n) * H + h] = s;
        g_adst[(m * NN + n) * H + h] = d;
    }
}

// ---------------- fused alpha + leaky_relu + exp + denom accumulate ----------------
template<int H>
__global__ void k_edge_ae(const int* __restrict__ ei_all, const float* __restrict__ attr) {
    int e = blockIdx.x * blockDim.x + threadIdx.x;
    if (e >= EE) return;
    int m = blockIdx.y;
    const int* ei = ei_all + m * 2 * EE;
    int s = ei[e], d = ei[EE + e];
    float ea = log1pf(attr[m * EE + e]) * g_stats[m * 4 + 2] + g_stats[m * 4 + 3];
    if (H == 4) {
        float4 as = *(const float4*)&g_asrc[(m * NN + s) * 4];
        float4 ad = *(const float4*)&g_adst[(m * NN + d) * 4];
        float4 ed = *(const float4*)&g_edot[m * 4];
        float4 r;
        r.x = lrelu_exp(as.x + ad.x + ea * ed.x);
        r.y = lrelu_exp(as.y + ad.y + ea * ed.y);
        r.z = lrelu_exp(as.z + ad.z + ea * ed.z);
        r.w = lrelu_exp(as.w + ad.w + ea * ed.w);
        *(float4*)&g_ex[(size_t)(m * EE + e) * 4] = r;
        red_add_v4(&g_denom[(m * NN + d) * 4], r.x, r.y, r.z, r.w);
    } else {
        float a = g_asrc[m * NN + s] + g_adst[m * NN + d] + ea * g_edot[m * H];
        float ex = lrelu_exp(a);
        g_ex[m * EE + e] = ex;
        atomicAdd(&g_denom[m * NN + d], ex);
    }
}

// ---------------- normalize: ex -> ex/denom[dst] ----------------
template<int H>
__global__ void k_edge_norm(const int* __restrict__ ei_all) {
    int e = blockIdx.x * blockDim.x + threadIdx.x;
    if (e >= EE) return;
    int m = blockIdx.y;
    const int* ei = ei_all + m * 2 * EE;
    int d = ei[EE + e];
    if (H == 4) {
        float4 ex = *(float4*)&g_ex[(size_t)(m * EE + e) * 4];
        float4 dn = *(const float4*)&g_denom[(m * NN + d) * 4];
        ex.x /= (dn.x + 1e-16f); ex.y /= (dn.y + 1e-16f);
        ex.z /= (dn.z + 1e-16f); ex.w /= (dn.w + 1e-16f);
        *(float4*)&g_ex[(size_t)(m * EE + e) * 4] = ex;
    } else {
        g_ex[m * EE + e] /= (g_denom[m * NN + d] + 1e-16f);
    }
}

// ---------------- agg[dst] += h[src] * w  (float4 reductions) ----------------
template<int H, int C>
__global__ void k_edge_agg(const int* __restrict__ ei_all) {
    constexpr int HC = H * C;
    constexpr int Q = HC / 4;       // 64 or 16, power of two
    int idx = blockIdx.x * blockDim.x + threadIdx.x;
    if (idx >= EE * Q) return;
    int m = blockIdx.y;
    int e = idx / Q;
    int q = idx - e * Q;
    const int* ei = ei_all + m * 2 * EE;
    int s = ei[e], d = ei[EE + e];
    int h = q / (C / 4);
    float w = g_ex[(size_t)(m * EE + e) * H + h];
    const float4 hv = *(const float4*)&g_h[(size_t)m * NN * HC + (size_t)s * HC + 4 * q];
    red_add_v4(&g_agg[(size_t)m * NN * HC + (size_t)d * HC + 4 * q],
               hv.x * w, hv.y * w, hv.z * w, hv.w * w);
}

// ---------------- head-mean + bias + elu -> zstack ----------------
template<int H, int C>
__global__ void k_node_fin(const float* __restrict__ bias) {
    int idx = blockIdx.x * blockDim.x + threadIdx.x;
    if (idx >= NN * C) return;
    int m = blockIdx.y;
    int n = idx / C, c = idx - n * C;
    float s = 0.f;
#pragma unroll
    for (int h = 0; h < H; h++)
        s += g_agg[(size_t)m * NN * H * C + (size_t)n * H * C + h * C + c];
    s = s * (1.f / H) + bias[m * C + c];
    g_zstack[(size_t)(n * MM + m) * C + c] = elu1(s);
}

// ---------------- semantic attention over M ----------------
__global__ void k_semantic(const float* __restrict__ semw, const float* __restrict__ semb,
                           const float* __restrict__ semv,
                           float* __restrict__ out, float* beta_out) {
    __shared__ float zs[MM][CC];
    __shared__ float red[CC];
    __shared__ float sc[MM];
    int n = blockIdx.x, c = threadIdx.x;
#pragma unroll
    for (int m = 0; m < MM; m++) zs[m][c] = g_zstack[(size_t)(n * MM + m) * CC + c];
    __syncthreads();
#pragma unroll
    for (int m = 0; m < MM; m++) {
        float acc = semb[c];
#pragma unroll 16
        for (int k = 0; k < CC; k++) acc += zs[m][k] * semw[k * CC + c];
        red[c] = tanhf(acc) * semv[c];
        __syncthreads();
        for (int s = 32; s; s >>= 1) {
            if (c < s) red[c] += red[c + s];
            __syncthreads();
        }
        if (c == 0) sc[m] = red[0];
        __syncthreads();
    }
    if (c == 0) {
        float mx = fmaxf(sc[0], fmaxf(sc[1], sc[2]));
        float e0 = expf(sc[0] - mx), e1 = expf(sc[1] - mx), e2 = expf(sc[2] - mx);
        float inv = 1.f / (e0 + e1 + e2);
        sc[0] = e0 * inv; sc[1] = e1 * inv; sc[2] = e2 * inv;
    }
    __syncthreads();
    out[n * CC + c] = zs[0][c] * sc[0] + zs[1][c] * sc[1] + zs[2][c] * sc[2];
    if (beta_out != nullptr && c < MM) beta_out[n * MM + c] = sc[c];
}

// ---------------- tiled fused decoder: xhat = elu(z@W1+b1)@W2+b2 ----------------
__global__ void k_decoder(const float* __restrict__ z,
                          const float* __restrict__ w1, const float* __restrict__ b1,
                          const float* __restrict__ w2, const float* __restrict__ b2,
                          float* __restrict__ xhat) {
    extern __shared__ float sm[];
    float* Ts  = sm;               // [64][65]
    float* Zs  = sm + 4160;        // [64][65]
    float* W1s = sm + 8320;        // [64][64]
    float* W2s = sm + 4160;        // [64][128], overlays Zs+W1s in phase 2
    int nb = blockIdx.x * 64;
    int tid = threadIdx.x;
    int tx = tid & 15, ty = tid >> 4;
    // load z tile and W1
#pragma unroll
    for (int i = 0; i < 4; i++) {
        int v = tid + i * 256;
        int row = v >> 4;
        int kq = (v & 15) << 2;
        int gr = nb + row;
        float4 zv = make_float4(0.f, 0.f, 0.f, 0.f);
        if (gr < NN) zv = *(const float4*)(z + gr * CC + kq);
        Zs[row * 65 + kq + 0] = zv.x; Zs[row * 65 + kq + 1] = zv.y;
        Zs[row * 65 + kq + 2] = zv.z; Zs[row * 65 + kq + 3] = zv.w;
        *(float4*)&W1s[(v >> 4) * 64 + kq] = *(const float4*)(w1 + (v >> 4) * CC + kq);
    }
    __syncthreads();
    // phase 1: T = elu(Z @ W1 + b1)
    {
        float acc[4][4];
#pragma unroll
        for (int j = 0; j < 4; j++) {
            float bv = b1[tx * 4 + j];
#pragma unroll
            for (int i = 0; i < 4; i++) acc[i][j] = bv;
        }
#pragma unroll 16
        for (int k = 0; k < 64; k++) {
            float a0 = Zs[(ty * 4 + 0) * 65 + k];
            float a1 = Zs[(ty * 4 + 1) * 65 + k];
            float a2 = Zs[(ty * 4 + 2) * 65 + k];
            float a3 = Zs[(ty * 4 + 3) * 65 + k];
            float4 b = *(float4*)&W1s[k * 64 + tx * 4];
            acc[0][0] += a0 * b.x; acc[0][1] += a0 * b.y; acc[0][2] += a0 * b.z; acc[0][3] += a0 * b.w;
            acc[1][0] += a1 * b.x; acc[1][1] += a1 * b.y; acc[1][2] += a1 * b.z; acc[1][3] += a1 * b.w;
            acc[2][0] += a2 * b.x; acc[2][1] += a2 * b.y; acc[2][2] += a2 * b.z; acc[2][3] += a2 * b.w;
            acc[3][0] += a3 * b.x; acc[3][1] += a3 * b.y; acc[3][2] += a3 * b.z; acc[3][3] += a3 * b.w;
        }
#pragma unroll
        for (int i = 0; i < 4; i++)
#pragma unroll
            for (int j = 0; j < 4; j++)
                Ts[(ty * 4 + i) * 65 + tx * 4 + j] = elu1(acc[i][j]);
    }
    __syncthreads();
    // load W2 (overwrites Zs/W1s)
#pragma unroll
    for (int i = 0; i < 8; i++) {
        int v = tid + i * 256;
        int k = v >> 5;
        int cq = (v & 31) << 2;
        *(float4*)&W2s[k * 128 + cq] = *(const float4*)(w2 + k * FIN + cq);
    }
    __syncthreads();
    // phase 2: xhat = T @ W2 + b2  (128 output cols: tx*4 and 64+tx*4)
    {
        float acc[4][8];
#pragma unroll
        for (int j = 0; j < 4; j++) {
            float bva = b2[tx * 4 + j], bvb = b2[64 + tx * 4 + j];
#pragma unroll
            for (int i = 0; i < 4; i++) { acc[i][j] = bva; acc[i][j + 4] = bvb; }
        }
#pragma unroll 8
        for (int k = 0; k < 64; k++) {
            float a0 = Ts[(ty * 4 + 0) * 65 + k];
            float a1 = Ts[(ty * 4 + 1) * 65 + k];
            float a2 = Ts[(ty * 4 + 2) * 65 + k];
            float a3 = Ts[(ty * 4 + 3) * 65 + k];
            float4 ba = *(float4*)&W2s[k * 128 + tx * 4];
            float4 bb = *(float4*)&W2s[k * 128 + 64 + tx * 4];
            acc[0][0] += a0 * ba.x; acc[0][1] += a0 * ba.y; acc[0][2] += a0 * ba.z; acc[0][3] += a0 * ba.w;
            acc[1][0] += a1 * ba.x; acc[1][1] += a1 * ba.y; acc[1][2] += a1 * ba.z; acc[1][3] += a1 * ba.w;
            acc[2][0] += a2 * ba.x; acc[2][1] += a2 * ba.y; acc[2][2] += a2 * ba.z; acc[2][3] += a2 * ba.w;
            acc[3][0] += a3 * ba.x; acc[3][1] += a3 * ba.y; acc[3][2] += a3 * ba.z; acc[3][3] += a3 * ba.w;
            acc[0][4] += a0 * bb.x; acc[0][5] += a0 * bb.y; acc[0][6] += a0 * bb.z; acc[0][7] += a0 * bb.w;
            acc[1][4] += a1 * bb.x; acc[1][5] += a1 * bb.y; acc[1][6] += a1 * bb.z; acc[1][7] += a1 * bb.w;
            acc[2][4] += a2 * bb.x; acc[2][5] += a2 * bb.y; acc[2][6] += a2 * bb.z; acc[2][7] += a2 * bb.w;
            acc[3][4] += a3 * bb.x; acc[3][5] += a3 * bb.y; acc[3][6] += a3 * bb.z; acc[3][7] += a3 * bb.w;
        }
#pragma unroll
        for (int i = 0; i < 4; i++) {
            int gr = nb + ty * 4 + i;
            if (gr < NN) {
                *(float4*)(xhat + (size_t)gr * FIN + tx * 4) =
                    make_float4(acc[i][0], acc[i][1], acc[i][2], acc[i][3]);
                *(float4*)(xhat + (size_t)gr * FIN + 64 + tx * 4) =
                    make_float4(acc[i][4], acc[i][5], acc[i][6], acc[i][7]);
            }
        }
    }
}

// ---------------- host ----------------
extern "C" void kernel_launch(void* const* d_in, const int* in_sizes, int n_in,
                              void* d_out, int out_size) {
    const float* x      = (const float*)d_in[0];
    const int*   ei     = (const int*)  d_in[1];   // [M,2,E]
    const float* eattr  = (const float*)d_in[2];   // [M,E,1]
    const float* lin1w  = (const float*)d_in[3];
    const float* a1s    = (const float*)d_in[4];
    const float* a1d    = (const float*)d_in[5];
    const float* l1e    = (const float*)d_in[6];
    const float* a1e    = (const float*)d_in[7];
    const float* b1     = (const float*)d_in[8];
    const float* bn1g   = (const float*)d_in[9];
    const float* bn1b   = (const float*)d_in[10];
    const float* sem1w  = (const float*)d_in[11];
    const float* sem1b  = (const float*)d_in[12];
    const float* sem1v  = (const float*)d_in[13];
    const float* lin2w  = (const float*)d_in[14];
    const float* a2s    = (const float*)d_in[15];
    const float* a2d    = (const float*)d_in[16];
    const float* l2e    = (const float*)d_in[17];
    const float* a2e    = (const float*)d_in[18];
    const float* b2     = (const float*)d_in[19];
    const float* bn2g   = (const float*)d_in[20];
    const float* bn2b   = (const float*)d_in[21];
    const float* sem2w  = (const float*)d_in[22];
    const float* sem2b  = (const float*)d_in[23];
    const float* sem2v  = (const float*)d_in[24];
    const float* dec1w  = (const float*)d_in[25];
    const float* dec1b  = (const float*)d_in[26];
    const float* dec2w  = (const float*)d_in[27];
    const float* dec2b  = (const float*)d_in[28];

    float* z_out    = (float*)d_out;             // [N, C2]
    float* xhat     = z_out + NN * CC;           // [N, IN]
    float* beta_out = xhat + NN * FIN;           // [N, M]

    float* houtp = nullptr;
    cudaGetSymbolAddress((void**)&houtp, g_hout);

    const int EB = (EE + 255) / 256;             // 1250

    // ================= HAN layer 1 (heads = 4) =================
    {
        int nagg4 = MM * NN * HH * CC / 4;       // 3.84M
        k_init<<<(nagg4 + 255) / 256, 256>>>(nagg4, MM * NN * HH, 1);
        k_bnstats<<<dim3(EB, MM), 256>>>(eattr);
        k_bnfin<HH, CC><<<1, MM * HH * 32>>>(l1e, a1e, bn1g, bn1b);
        k_sgemm<FIN, HH * CC><<<dim3((HH * CC) / 64, (NN + 63) / 64, MM), 256>>>(x, lin1w);
        k_attdot<HH, CC><<<dim3(NN, MM), HH * CC>>>(a1s, a1d);
        k_edge_ae<HH><<<dim3(EB, MM), 256>>>(ei, eattr);
        k_edge_norm<HH><<<dim3(EB, MM), 256>>>(ei);
        k_edge_agg<HH, CC><<<dim3(EE * (HH * CC / 4) / 256, MM), 256>>>(ei);
        k_node_fin<HH, CC><<<dim3((NN * CC + 255) / 256, MM), 256>>>(b1);
        k_semantic<<<NN, CC>>>(sem1w, sem1b, sem1v, houtp, nullptr);
    }

    // ================= HAN layer 2 (heads = 1) =================
    {
        int nagg4 = MM * NN * CC / 4;
        k_init<<<(nagg4 + 255) / 256, 256>>>(nagg4, MM * NN, 0);
        k_bnfin<1, CC><<<1, MM * 32>>>(l2e, a2e, bn2g, bn2b);
        k_sgemm<CC, CC><<<dim3(1, (NN + 63) / 64, MM), 256>>>(houtp, lin2w);
        k_attdot<1, CC><<<dim3(NN, MM), CC>>>(a2s, a2d);
        k_edge_ae<1><<<dim3(EB, MM), 256>>>(ei, eattr);
        k_edge_norm<1><<<dim3(EB, MM), 256>>>(ei);
        k_edge_agg<1, CC><<<dim3(EE * (CC / 4) / 256, MM), 256>>>(ei);
        k_node_fin<1, CC><<<dim3((NN * CC + 255) / 256, MM), 256>>>(b2);
        k_semantic<<<NN, CC>>>(sem2w, sem2b, sem2v, z_out, beta_out);
    }

    // ================= decoder =================
    static bool attr_set = false;
    if (!attr_set) {
        cudaFuncSetAttribute(k_decoder, cudaFuncAttributeMaxDynamicSharedMemorySize, 12416 * 4);
        attr_set = true;
    }
    k_decoder<<<(NN + 63) / 64, 256, 12416 * 4>>>(z_out, dec1w, dec1b, dec2w, dec2b, xhat);
}

// round 3
// speedup vs baseline: 1.8062x; 1.2217x over previous
#include <cuda_runtime.h>
#include <math.h>
#include <float.h>

#define NN 20000
#define EE 320000
#define MM 3
#define FIN 128
#define HH 4
#define CC 64
#define NEG_SLOPE 0.2f

// ---------------- scratch (device globals) ----------------
__device__ __align__(16) float g_h[MM * NN * HH * CC];     // projected features
__device__ __align__(16) float g_asrc[MM * NN * HH];
__device__ __align__(16) float g_adst[MM * NN * HH];
__device__ __align__(16) float g_ex[MM * EE * HH];         // exp(alpha) in CSR order (slow path only)
__device__ __align__(16) float g_zstack[NN * MM * CC];
__device__ __align__(16) float g_hout[NN * CC];
__device__ float g_stats[MM * 4];                           // per m: sum, sumsq, scale, shift
__device__ float g_edot[MM * HH];
// CSR
__device__ int g_deg[MM * NN];
__device__ int g_rowptr[MM * (NN + 1)];
__device__ int g_cursor[MM * NN];
__device__ int g_csr[MM * EE];

// ---------------- helpers ----------------
__device__ __forceinline__ float elu1(float x) { return x > 0.f ? x : expm1f(x); }
__device__ __forceinline__ float lrelu_exp(float a) {
    a = a > 0.f ? a : NEG_SLOPE * a;
    return expf(a);
}

// ---------------- zero init ----------------
__global__ void k_zero1() {
    int i = blockIdx.x * blockDim.x + threadIdx.x;
    if (i < MM * NN) g_deg[i] = 0;
    if (i < MM * 4) g_stats[i] = 0.f;
}

// ---------------- CSR: histogram ----------------
__global__ void k_hist(const int* __restrict__ ei_all) {
    int e = blockIdx.x * 256 + threadIdx.x;
    if (e >= EE) return;
    int m = blockIdx.y;
    atomicAdd(&g_deg[m * NN + ei_all[m * 2 * EE + EE + e]], 1);
}

// ---------------- CSR: exclusive scan (one block per metapath) ----------------
__global__ void k_scan() {
    int m = blockIdx.x;
    __shared__ int swarp[32];
    int tid = threadIdx.x, lane = tid & 31, w = tid >> 5;
    int carry = 0;
    if (tid == 0) g_rowptr[m * (NN + 1)] = 0;
    for (int c0 = 0; c0 < NN; c0 += 1024) {
        int i = c0 + tid;
        int v = (i < NN) ? g_deg[m * NN + i] : 0;
        int incl = v;
#pragma unroll
        for (int off = 1; off < 32; off <<= 1) {
            int t = __shfl_up_sync(0xffffffffu, incl, off);
            if (lane >= off) incl += t;
        }
        if (lane == 31) swarp[w] = incl;
        __syncthreads();
        if (w == 0) {
            int x = swarp[lane];
#pragma unroll
            for (int off = 1; off < 32; off <<= 1) {
                int t = __shfl_up_sync(0xffffffffu, x, off);
                if (lane >= off) x += t;
            }
            swarp[lane] = x;
        }
        __syncthreads();
        int offset = (w > 0) ? swarp[w - 1] : 0;
        int total = swarp[31];
        incl += offset;
        if (i < NN) {
            g_rowptr[m * (NN + 1) + i + 1] = carry + incl;
            g_cursor[m * NN + i] = carry + incl - v;
        }
        carry += total;
        __syncthreads();
    }
}

// ---------------- CSR: scatter edge ids ----------------
__global__ void k_scatter(const int* __restrict__ ei_all) {
    int e = blockIdx.x * 256 + threadIdx.x;
    if (e >= EE) return;
    int m = blockIdx.y;
    int d = ei_all[m * 2 * EE + EE + e];
    int pos = atomicAdd(&g_cursor[m * NN + d], 1);
    g_csr[(size_t)m * EE + pos] = e;
}

// ---------------- BN statistics of log1p(edge_attr) ----------------
__global__ void k_bnstats(const float* __restrict__ attr) {
    int m = blockIdx.y;
    int i = blockIdx.x * blockDim.x + threadIdx.x;
    float v = 0.f, v2 = 0.f;
    if (i < EE) { float t = log1pf(attr[m * EE + i]); v = t; v2 = t * t; }
#pragma unroll
    for (int o = 16; o; o >>= 1) {
        v  += __shfl_down_sync(0xffffffffu, v,  o);
        v2 += __shfl_down_sync(0xffffffffu, v2, o);
    }
    __shared__ float s1[8], s2[8];
    int lane = threadIdx.x & 31, w = threadIdx.x >> 5;
    if (lane == 0) { s1[w] = v; s2[w] = v2; }
    __syncthreads();
    if (threadIdx.x == 0) {
        float a = 0.f, b = 0.f;
        for (int j = 0; j < 8; j++) { a += s1[j]; b += s2[j]; }
        atomicAdd(&g_stats[m * 4 + 0], a);
        atomicAdd(&g_stats[m * 4 + 1], b);
    }
}

// ---------------- finalize BN affine + per-head edge scalar ----------------
template<int H, int C>
__global__ void k_bnfin(const float* __restrict__ lew, const float* __restrict__ aew,
                        const float* __restrict__ gamma, const float* __restrict__ beta) {
    int w = threadIdx.x >> 5, lane = threadIdx.x & 31;   // MM*H warps
    int m = w / H, h = w % H;
    float s = 0.f;
    for (int c = lane; c < C; c += 32)
        s += lew[(m * H + h) * C + c] * aew[(m * H + h) * C + c];
#pragma unroll
    for (int o = 16; o; o >>= 1) s += __shfl_down_sync(0xffffffffu, s, o);
    if (lane == 0) g_edot[m * H + h] = s;
    if (threadIdx.x < MM) {
        int mm = threadIdx.x;
        float mu   = g_stats[mm * 4 + 0] * (1.f / EE);
        float var  = g_stats[mm * 4 + 1] * (1.f / EE) - mu * mu;
        float sc   = gamma[mm] * rsqrtf(var + 1e-5f);
        g_stats[mm * 4 + 2] = sc;
        g_stats[mm * 4 + 3] = beta[mm] - mu * sc;
    }
}

// ---------------- SGEMM + fused attention-dot epilogue ----------------
// tile: 64 nodes x CT cols, 256 threads, thread = 4 nodes x (CT/16) cols
template<int K, int NC, int CT, int H>
__global__ void k_sgemm(const float* __restrict__ X, const float* __restrict__ Wall,
                        const float* __restrict__ asw, const float* __restrict__ adw) {
    constexpr int CP = CT / 16;      // cols per thread: 8 (CT=128) or 4 (CT=64)
    constexpr int RW = 64 / CP;      // shfl reduce width covering one head: 8 or 16
    extern __shared__ float sm[];
    float* Xs = sm;                  // [64][68]
    float* Ws = sm + 64 * 68;        // [64][CT]
    int m = blockIdx.z;
    const float* W = Wall + (size_t)m * K * NC;
    float* Hd = g_h + (size_t)m * NN * NC;
    int nb = blockIdx.y * 64, cb = blockIdx.x * CT;
    int tid = threadIdx.x, tx = tid & 15, ty = tid >> 4;
    float acc[4][CP];
#pragma unroll
    for (int i = 0; i < 4; i++)
#pragma unroll
        for (int j = 0; j < CP; j++) acc[i][j] = 0.f;

    for (int kt = 0; kt < K; kt += 64) {
        // X tile: 64 nodes x 64 k
#pragma unroll
        for (int i = 0; i < 4; i++) {
            int v = tid + i * 256;
            int row = v >> 4, kq = (v & 15) << 2;
            int gr = nb + row;
            float4 xv = make_float4(0.f, 0.f, 0.f, 0.f);
            if (gr < NN) xv = *(const float4*)(X + (size_t)gr * K + kt + kq);
            *(float4*)&Xs[row * 68 + kq] = xv;
        }
        // W tile: 64 k x CT cols
#pragma unroll
        for (int i = 0; i < CP; i++) {
            int v = tid + i * 256;
            int krow = v / (CT / 4), cq = (v % (CT / 4)) * 4;
            *(float4*)&Ws[krow * CT + cq] = *(const float4*)(W + (size_t)(kt + krow) * NC + cb + cq);
        }
        __syncthreads();
#pragma unroll 8
        for (int k = 0; k < 64; k++) {
            float a[4];
#pragma unroll
            for (int i = 0; i < 4; i++) a[i] = Xs[(ty * 4 + i) * 68 + k];
            float b[CP];
#pragma unroll
            for (int jj = 0; jj < CP / 4; jj++) {
                float4 bv = *(float4*)&Ws[k * CT + tx * CP + 4 * jj];
                b[4 * jj + 0] = bv.x; b[4 * jj + 1] = bv.y;
                b[4 * jj + 2] = bv.z; b[4 * jj + 3] = bv.w;
            }
#pragma unroll
            for (int i = 0; i < 4; i++)
#pragma unroll
                for (int j = 0; j < CP; j++) acc[i][j] += a[i] * b[j];
        }
        __syncthreads();
    }
    // store h
#pragma unroll
    for (int i = 0; i < 4; i++) {
        int gr = nb + ty * 4 + i;
        if (gr < NN) {
#pragma unroll
            for (int jj = 0; jj < CP / 4; jj++)
                *(float4*)(Hd + (size_t)gr * NC + cb + tx * CP + 4 * jj) =
                    make_float4(acc[i][4 * jj], acc[i][4 * jj + 1], acc[i][4 * jj + 2], acc[i][4 * jj + 3]);
        }
    }
    // fused attention dots: each (node, head) covered by exactly one reduce group -> plain store
    int colbase = cb + tx * CP;
    int head = colbase / 64;
#pragma unroll
    for (int i = 0; i < 4; i++) {
        float ps = 0.f, pd = 0.f;
#pragma unroll
        for (int j = 0; j < CP; j++) {
            ps += acc[i][j] * asw[m * H * 64 + colbase + j];
            pd += acc[i][j] * adw[m * H * 64 + colbase + j];
        }
#pragma unroll
        for (int off = RW / 2; off; off >>= 1) {
            ps += __shfl_down_sync(0xffffffffu, ps, off, RW);
            pd += __shfl_down_sync(0xffffffffu, pd, off, RW);
        }
        int gr = nb + ty * 4 + i;
        if ((tx & (RW - 1)) == 0 && gr < NN) {
            g_asrc[(size_t)(m * NN + gr) * H + head] = ps;
            g_adst[(size_t)(m * NN + gr) * H + head] = pd;
        }
    }
}

// ---------------- fused GAT: alpha + softmax + aggregate + mean + bias + elu ----
// one block per (node, metapath); blockDim = H*C threads (channel per thread)
template<int H, int C>
__global__ void k_gat(const int* __restrict__ ei_all, const float* __restrict__ attr,
                      const float* __restrict__ bias) {
    constexpr int HC = H * C;
    constexpr int NW = HC / 32;
    __shared__ int   s_soff[64];
    __shared__ float s_w[64 * H];
    __shared__ float s_red[NW * H];
    __shared__ float s_inv[H];
    __shared__ float s_acc[HC];
    int n = blockIdx.x, m = blockIdx.y;
    int tid = threadIdx.x;
    const int* ei  = ei_all + m * 2 * EE;
    const int* csr = g_csr + (size_t)m * EE;
    int base = g_rowptr[m * (NN + 1) + n];
    int deg  = g_rowptr[m * (NN + 1) + n + 1] - base;
    float sc = g_stats[m * 4 + 2], sh = g_stats[m * 4 + 3];
    float adst[H], edot[H];
#pragma unroll
    for (int h = 0; h < H; h++) {
        adst[h] = g_adst[(size_t)(m * NN + n) * H + h];
        edot[h] = g_edot[m * H + h];
    }
    const float* hbase = g_h + (size_t)m * NN * HC;
    float den[H];
#pragma unroll
    for (int h = 0; h < H; h++) den[h] = 0.f;

    bool fast = (deg <= 64);
    // ---------- phase 1: ex + denom ----------
    if (fast) {
        if (tid < deg) {
            int eid = csr[base + tid];
            s_soff[tid] = ei[eid] * HC;
            float ea = log1pf(attr[m * EE + eid]) * sc + sh;
            if (H == 4) {
                float4 as = *(const float4*)&g_asrc[(size_t)(m * NN + ei[eid]) * 4];
                float e0 = lrelu_exp(as.x + adst[0] + ea * edot[0]);
                float e1 = lrelu_exp(as.y + adst[1] + ea * edot[1]);
                float e2 = lrelu_exp(as.z + adst[2] + ea * edot[2]);
                float e3 = lrelu_exp(as.w + adst[3] + ea * edot[3]);
                s_w[tid * 4 + 0] = e0; s_w[tid * 4 + 1] = e1;
                s_w[tid * 4 + 2] = e2; s_w[tid * 4 + 3] = e3;
                den[0] = e0; den[1] = e1; den[2] = e2; den[3] = e3;
            } else {
                float e0 = lrelu_exp(g_asrc[m * NN + ei[eid]] + adst[0] + ea * edot[0]);
                s_w[tid] = e0;
                den[0] = e0;
            }
        }
    } else {
        for (int j = tid; j < deg; j += HC) {
            int eid = csr[base + j];
            float ea = log1pf(attr[m * EE + eid]) * sc + sh;
#pragma unroll
            for (int h = 0; h < H; h++) {
                float a = g_asrc[(size_t)(m * NN + ei[eid]) * H + h] + adst[h] + ea * edot[h];
                a = lrelu_exp(a);
                g_ex[((size_t)m * EE + base + j) * H + h] = a;
                den[h] += a;
            }
        }
    }
    // block reduce denom
#pragma unroll
    for (int h = 0; h < H; h++)
#pragma unroll
        for (int o = 16; o; o >>= 1) den[h] += __shfl_down_sync(0xffffffffu, den[h], o);
    int lane = tid & 31, w = tid >> 5;
    if (lane == 0)
#pragma unroll
        for (int h = 0; h < H; h++) s_red[w * H + h] = den[h];
    __syncthreads();
    if (tid == 0) {
#pragma unroll
        for (int h = 0; h < H; h++) {
            float t = 0.f;
            for (int ww = 0; ww < NW; ww++) t += s_red[ww * H + h];
            s_inv[h] = 1.f / (t + 1e-16f);
        }
    }
    __syncthreads();

    // ---------- phase 2: weighted aggregation ----------
    int myh = tid / C;
    float acc = 0.f;
    if (fast) {
        if (tid < deg) {
#pragma unroll
            for (int h = 0; h < H; h++) s_w[tid * H + h] *= s_inv[h];
        }
        __syncthreads();
#pragma unroll 4
        for (int j = 0; j < deg; j++)
            acc += s_w[j * H + myh] * hbase[s_soff[j] + tid];
    } else {
        for (int cs = 0; cs < deg; cs += 64) {
            int cn = min(64, deg - cs);
            if (tid < cn) {
                int eid = csr[base + cs + tid];
                s_soff[tid] = ei[eid] * HC;
#pragma unroll
                for (int h = 0; h < H; h++)
                    s_w[tid * H + h] = g_ex[((size_t)m * EE + base + cs + tid) * H + h] * s_inv[h];
            }
            __syncthreads();
#pragma unroll 4
            for (int j = 0; j < cn; j++)
                acc += s_w[j * H + myh] * hbase[s_soff[j] + tid];
            __syncthreads();
        }
    }
    // ---------- head mean + bias + elu ----------
    if (H == 1) {
        g_zstack[((size_t)n * MM + m) * C + tid] = elu1(acc + bias[m * C + tid]);
    } else {
        s_acc[tid] = acc;
        __syncthreads();
        if (tid < C) {
            float t = 0.f;
#pragma unroll
            for (int h = 0; h < H; h++) t += s_acc[h * C + tid];
            g_zstack[((size_t)n * MM + m) * C + tid] = elu1(t * (1.f / H) + bias[m * C + tid]);
        }
    }
}

// ---------------- semantic attention over M (4 nodes per block) ----------------
__global__ void k_semantic(const float* __restrict__ semw, const float* __restrict__ semb,
                           const float* __restrict__ semv,
                           float* __restrict__ out, float* beta_out) {
    __shared__ float zsh[4][MM][CC];
    __shared__ float wred[4][2];
    __shared__ float ssc[4][MM];
    int g = threadIdx.x >> 6, c = threadIdx.x & 63;
    int n = blockIdx.x * 4 + g;
    bool ok = n < NN;
#pragma unroll
    for (int m = 0; m < MM; m++)
        zsh[g][m][c] = ok ? g_zstack[((size_t)n * MM + m) * CC + c] : 0.f;
    __syncthreads();
#pragma unroll
    for (int m = 0; m < MM; m++) {
        float acc = semb[c];
#pragma unroll 16
        for (int k = 0; k < CC; k++) acc += zsh[g][m][k] * semw[k * CC + c];
        float v = tanhf(acc) * semv[c];
#pragma unroll
        for (int o = 16; o; o >>= 1) v += __shfl_down_sync(0xffffffffu, v, o);
        if ((c & 31) == 0) wred[g][c >> 5] = v;
        __syncthreads();
        if (c == 0) ssc[g][m] = wred[g][0] + wred[g][1];
        __syncthreads();
    }
    if (c == 0) {
        float mx = fmaxf(ssc[g][0], fmaxf(ssc[g][1], ssc[g][2]));
        float e0 = expf(ssc[g][0] - mx), e1 = expf(ssc[g][1] - mx), e2 = expf(ssc[g][2] - mx);
        float inv = 1.f / (e0 + e1 + e2);
        ssc[g][0] = e0 * inv; ssc[g][1] = e1 * inv; ssc[g][2] = e2 * inv;
    }
    __syncthreads();
    if (ok) {
        out[(size_t)n * CC + c] = zsh[g][0][c] * ssc[g][0] + zsh[g][1][c] * ssc[g][1] + zsh[g][2][c] * ssc[g][2];
        if (beta_out != nullptr && c < MM) beta_out[n * MM + c] = ssc[g][c];
    }
}

// ---------------- tiled fused decoder ----------------
__global__ void k_decoder(const float* __restrict__ z,
                          const float* __restrict__ w1, const float* __restrict__ b1,
                          const float* __restrict__ w2, const float* __restrict__ b2,
                          float* __restrict__ xhat) {
    extern __shared__ float sm[];
    float* Ts  = sm;               // [64][65]
    float* Zs  = sm + 4160;        // [64][65]
    float* W1s = sm + 8320;        // [64][64]
    float* W2s = sm + 4160;        // [64][128], overlays phase-1 space
    int nb = blockIdx.x * 64;
    int tid = threadIdx.x;
    int tx = tid & 15, ty = tid >> 4;
#pragma unroll
    for (int i = 0; i < 4; i++) {
        int v = tid + i * 256;
        int row = v >> 4, kq = (v & 15) << 2;
        int gr = nb + row;
        float4 zv = make_float4(0.f, 0.f, 0.f, 0.f);
        if (gr < NN) zv = *(const float4*)(z + (size_t)gr * CC + kq);
        Zs[row * 65 + kq + 0] = zv.x; Zs[row * 65 + kq + 1] = zv.y;
        Zs[row * 65 + kq + 2] = zv.z; Zs[row * 65 + kq + 3] = zv.w;
        *(float4*)&W1s[row * 64 + kq] = *(const float4*)(w1 + row * CC + kq);
    }
    __syncthreads();
    {
        float acc[4][4];
#pragma unroll
        for (int j = 0; j < 4; j++) {
            float bv = b1[tx * 4 + j];
#pragma unroll
            for (int i = 0; i < 4; i++) acc[i][j] = bv;
        }
#pragma unroll 16
        for (int k = 0; k < 64; k++) {
            float a0 = Zs[(ty * 4 + 0) * 65 + k];
            float a1 = Zs[(ty * 4 + 1) * 65 + k];
            float a2 = Zs[(ty * 4 + 2) * 65 + k];
            float a3 = Zs[(ty * 4 + 3) * 65 + k];
            float4 b = *(float4*)&W1s[k * 64 + tx * 4];
            acc[0][0] += a0 * b.x; acc[0][1] += a0 * b.y; acc[0][2] += a0 * b.z; acc[0][3] += a0 * b.w;
            acc[1][0] += a1 * b.x; acc[1][1] += a1 * b.y; acc[1][2] += a1 * b.z; acc[1][3] += a1 * b.w;
            acc[2][0] += a2 * b.x; acc[2][1] += a2 * b.y; acc[2][2] += a2 * b.z; acc[2][3] += a2 * b.w;
            acc[3][0] += a3 * b.x; acc[3][1] += a3 * b.y; acc[3][2] += a3 * b.z; acc[3][3] += a3 * b.w;
        }
#pragma unroll
        for (int i = 0; i < 4; i++)
#pragma unroll
            for (int j = 0; j < 4; j++)
                Ts[(ty * 4 + i) * 65 + tx * 4 + j] = elu1(acc[i][j]);
    }
    __syncthreads();
#pragma unroll
    for (int i = 0; i < 8; i++) {
        int v = tid + i * 256;
        int k = v >> 5, cq = (v & 31) << 2;
        *(float4*)&W2s[k * 128 + cq] = *(const float4*)(w2 + k * FIN + cq);
    }
    __syncthreads();
    {
        float acc[4][8];
#pragma unroll
        for (int j = 0; j < 4; j++) {
            float bva = b2[tx * 4 + j], bvb = b2[64 + tx * 4 + j];
#pragma unroll
            for (int i = 0; i < 4; i++) { acc[i][j] = bva; acc[i][j + 4] = bvb; }
        }
#pragma unroll 8
        for (int k = 0; k < 64; k++) {
            float a0 = Ts[(ty * 4 + 0) * 65 + k];
            float a1 = Ts[(ty * 4 + 1) * 65 + k];
            float a2 = Ts[(ty * 4 + 2) * 65 + k];
            float a3 = Ts[(ty * 4 + 3) * 65 + k];
            float4 ba = *(float4*)&W2s[k * 128 + tx * 4];
            float4 bb = *(float4*)&W2s[k * 128 + 64 + tx * 4];
            acc[0][0] += a0 * ba.x; acc[0][1] += a0 * ba.y; acc[0][2] += a0 * ba.z; acc[0][3] += a0 * ba.w;
            acc[1][0] += a1 * ba.x; acc[1][1] += a1 * ba.y; acc[1][2] += a1 * ba.z; acc[1][3] += a1 * ba.w;
            acc[2][0] += a2 * ba.x; acc[2][1] += a2 * ba.y; acc[2][2] += a2 * ba.z; acc[2][3] += a2 * ba.w;
            acc[3][0] += a3 * ba.x; acc[3][1] += a3 * ba.y; acc[3][2] += a3 * ba.z; acc[3][3] += a3 * ba.w;
            acc[0][4] += a0 * bb.x; acc[0][5] += a0 * bb.y; acc[0][6] += a0 * bb.z; acc[0][7] += a0 * bb.w;
            acc[1][4] += a1 * bb.x; acc[1][5] += a1 * bb.y; acc[1][6] += a1 * bb.z; acc[1][7] += a1 * bb.w;
            acc[2][4] += a2 * bb.x; acc[2][5] += a2 * bb.y; acc[2][6] += a2 * bb.z; acc[2][7] += a2 * bb.w;
            acc[3][4] += a3 * bb.x; acc[3][5] += a3 * bb.y; acc[3][6] += a3 * bb.z; acc[3][7] += a3 * bb.w;
        }
#pragma unroll
        for (int i = 0; i < 4; i++) {
            int gr = nb + ty * 4 + i;
            if (gr < NN) {
                *(float4*)(xhat + (size_t)gr * FIN + tx * 4) =
                    make_float4(acc[i][0], acc[i][1], acc[i][2], acc[i][3]);
                *(float4*)(xhat + (size_t)gr * FIN + 64 + tx * 4) =
                    make_float4(acc[i][4], acc[i][5], acc[i][6], acc[i][7]);
            }
        }
    }
}

// ---------------- host ----------------
extern "C" void kernel_launch(void* const* d_in, const int* in_sizes, int n_in,
                              void* d_out, int out_size) {
    const float* x      = (const float*)d_in[0];
    const int*   ei     = (const int*)  d_in[1];   // [M,2,E]
    const float* eattr  = (const float*)d_in[2];   // [M,E,1]
    const float* lin1w  = (const float*)d_in[3];
    const float* a1s    = (const float*)d_in[4];
    const float* a1d    = (const float*)d_in[5];
    const float* l1e    = (const float*)d_in[6];
    const float* a1e    = (const float*)d_in[7];
    const float* b1     = (const float*)d_in[8];
    const float* bn1g   = (const float*)d_in[9];
    const float* bn1b   = (const float*)d_in[10];
    const float* sem1w  = (const float*)d_in[11];
    const float* sem1b  = (const float*)d_in[12];
    const float* sem1v  = (const float*)d_in[13];
    const float* lin2w  = (const float*)d_in[14];
    const float* a2s    = (const float*)d_in[15];
    const float* a2d    = (const float*)d_in[16];
    const float* l2e    = (const float*)d_in[17];
    const float* a2e    = (const float*)d_in[18];
    const float* b2     = (const float*)d_in[19];
    const float* bn2g   = (const float*)d_in[20];
    const float* bn2b   = (const float*)d_in[21];
    const float* sem2w  = (const float*)d_in[22];
    const float* sem2b  = (const float*)d_in[23];
    const float* sem2v  = (const float*)d_in[24];
    const float* dec1w  = (const float*)d_in[25];
    const float* dec1b  = (const float*)d_in[26];
    const float* dec2w  = (const float*)d_in[27];
    const float* dec2b  = (const float*)d_in[28];

    float* z_out    = (float*)d_out;             // [N, C2]
    float* xhat     = z_out + NN * CC;           // [N, IN]
    float* beta_out = xhat + NN * FIN;           // [N, M]

    float* houtp = nullptr;
    cudaGetSymbolAddress((void**)&houtp, g_hout);

    const int EB = (EE + 255) / 256;
    const int NB64 = (NN + 63) / 64;

    int smem1 = (64 * 68 + 64 * 128) * 4;   // 50176
    int smem2 = (64 * 68 + 64 * 64) * 4;    // 33792
    cudaFuncSetAttribute(k_sgemm<FIN, HH * CC, 128, HH>, cudaFuncAttributeMaxDynamicSharedMemorySize, smem1);
    cudaFuncSetAttribute(k_sgemm<CC, CC, 64, 1>, cudaFuncAttributeMaxDynamicSharedMemorySize, smem2);
    cudaFuncSetAttribute(k_decoder, cudaFuncAttributeMaxDynamicSharedMemorySize, 12416 * 4);

    // ---- CSR build (shared by both layers) + BN stats ----
    k_zero1<<<(MM * NN + 255) / 256, 256>>>();
    k_hist<<<dim3(EB, MM), 256>>>(ei);
    k_scan<<<MM, 1024>>>();
    k_scatter<<<dim3(EB, MM), 256>>>(ei);
    k_bnstats<<<dim3(EB, MM), 256>>>(eattr);

    // ---- HAN layer 1 (heads = 4) ----
    k_bnfin<HH, CC><<<1, MM * HH * 32>>>(l1e, a1e, bn1g, bn1b);
    k_sgemm<FIN, HH * CC, 128, HH><<<dim3(2, NB64, MM), 256, smem1>>>(x, lin1w, a1s, a1d);
    k_gat<HH, CC><<<dim3(NN, MM), HH * CC>>>(ei, eattr, b1);
    k_semantic<<<(NN + 3) / 4, 256>>>(sem1w, sem1b, sem1v, houtp, nullptr);

    // ---- HAN layer 2 (heads = 1) ----
    k_bnfin<1, CC><<<1, MM * 32>>>(l2e, a2e, bn2g, bn2b);
    k_sgemm<CC, CC, 64, 1><<<dim3(1, NB64, MM), 256, smem2>>>(houtp, lin2w, a2s, a2d);
    k_gat<1, CC><<<dim3(NN, MM), CC>>>(ei, eattr, b2);
    k_semantic<<<(NN + 3) / 4, 256>>>(sem2w, sem2b, sem2v, z_out, beta_out);

    // ---- decoder ----
    k_decoder<<<NB64, 256, 12416 * 4>>>(z_out, dec1w, dec1b, dec2w, dec2b, xhat);
}

// round 5
// speedup vs baseline: 2.5287x; 1.4000x over previous
#include <cuda_runtime.h>
#include <math.h>
#include <float.h>

#define NN 20000
#define EE 320000
#define MM 3
#define FIN 128
#define HH 4
#define CC 64
#define NEG_SLOPE 0.2f

// ---------------- scratch (device globals) ----------------
__device__ __align__(16) float g_h[MM * NN * HH * CC];     // projected features
__device__ __align__(16) float g_asrc[MM * NN * HH];
__device__ __align__(16) float g_adst[MM * NN * HH];
__device__ __align__(16) float g_zstack[NN * MM * CC];
__device__ __align__(16) float g_hout[NN * CC];
__device__ float g_stats[MM * 4];                           // per m: sum, sumsq, scale, shift
__device__ float g_edot[MM * HH];
// CSR (payload scattered directly: src index + log1p(attr) in CSR order)
__device__ int   g_deg[MM * NN];
__device__ int   g_rowptr[MM * (NN + 1)];
__device__ int   g_cursor[MM * NN];
__device__ int   g_src[MM * EE];
__device__ float g_lea[MM * EE];     // log1p(attr), edge order
__device__ float g_cea[MM * EE];     // log1p(attr), CSR order

// ---------------- helpers ----------------
__device__ __forceinline__ float elu1(float x) { return x > 0.f ? x : expm1f(x); }
__device__ __forceinline__ float lrelu_exp(float a) {
    a = a > 0.f ? a : NEG_SLOPE * a;
    return expf(a);
}

// ---------------- zero init ----------------
__global__ void k_zero1() {
    int i = blockIdx.x * blockDim.x + threadIdx.x;
    if (i < MM * NN) g_deg[i] = 0;
    if (i < MM * 4) g_stats[i] = 0.f;
}

// ---------------- fused: degree histogram + log1p + BN stats ----------------
__global__ void k_build(const int* __restrict__ ei_all, const float* __restrict__ attr) {
    int m = blockIdx.y;
    int e = blockIdx.x * 256 + threadIdx.x;
    float v = 0.f, v2 = 0.f;
    if (e < EE) {
        atomicAdd(&g_deg[m * NN + ei_all[m * 2 * EE + EE + e]], 1);
        float t = log1pf(attr[m * EE + e]);
        g_lea[(size_t)m * EE + e] = t;
        v = t; v2 = t * t;
    }
#pragma unroll
    for (int o = 16; o; o >>= 1) {
        v  += __shfl_down_sync(0xffffffffu, v,  o);
        v2 += __shfl_down_sync(0xffffffffu, v2, o);
    }
    __shared__ float s1[8], s2[8];
    int lane = threadIdx.x & 31, w = threadIdx.x >> 5;
    if (lane == 0) { s1[w] = v; s2[w] = v2; }
    __syncthreads();
    if (threadIdx.x == 0) {
        float a = 0.f, b = 0.f;
        for (int j = 0; j < 8; j++) { a += s1[j]; b += s2[j]; }
        atomicAdd(&g_stats[m * 4 + 0], a);
        atomicAdd(&g_stats[m * 4 + 1], b);
    }
}

// ---------------- CSR: exclusive scan (one block per metapath) ----------------
__global__ void k_scan() {
    int m = blockIdx.x;
    __shared__ int swarp[32];
    int tid = threadIdx.x, lane = tid & 31, w = tid >> 5;
    int carry = 0;
    if (tid == 0) g_rowptr[m * (NN + 1)] = 0;
    for (int c0 = 0; c0 < NN; c0 += 1024) {
        int i = c0 + tid;
        int v = (i < NN) ? g_deg[m * NN + i] : 0;
        int incl = v;
#pragma unroll
        for (int off = 1; off < 32; off <<= 1) {
            int t = __shfl_up_sync(0xffffffffu, incl, off);
            if (lane >= off) incl += t;
        }
        if (lane == 31) swarp[w] = incl;
        __syncthreads();
        if (w == 0) {
            int x = swarp[lane];
#pragma unroll
            for (int off = 1; off < 32; off <<= 1) {
                int t = __shfl_up_sync(0xffffffffu, x, off);
                if (lane >= off) x += t;
            }
            swarp[lane] = x;
        }
        __syncthreads();
        int offset = (w > 0) ? swarp[w - 1] : 0;
        int total = swarp[31];
        incl += offset;
        if (i < NN) {
            g_rowptr[m * (NN + 1) + i + 1] = carry + incl;
            g_cursor[m * NN + i] = carry + incl - v;
        }
        carry += total;
        __syncthreads();
    }
}

// ---------------- CSR: scatter src + log1p(attr) payload ----------------
__global__ void k_scatter(const int* __restrict__ ei_all) {
    int e = blockIdx.x * 256 + threadIdx.x;
    if (e >= EE) return;
    int m = blockIdx.y;
    int s = ei_all[m * 2 * EE + e];
    int d = ei_all[m * 2 * EE + EE + e];
    int pos = atomicAdd(&g_cursor[m * NN + d], 1);
    g_src[(size_t)m * EE + pos] = s;
    g_cea[(size_t)m * EE + pos] = g_lea[(size_t)m * EE + e];
}

// ---------------- finalize BN affine + per-head edge scalar ----------------
template<int H, int C>
__global__ void k_bnfin(const float* __restrict__ lew, const float* __restrict__ aew,
                        const float* __restrict__ gamma, const float* __restrict__ beta) {
    int w = threadIdx.x >> 5, lane = threadIdx.x & 31;   // MM*H warps
    int m = w / H, h = w % H;
    float s = 0.f;
    for (int c = lane; c < C; c += 32)
        s += lew[(m * H + h) * C + c] * aew[(m * H + h) * C + c];
#pragma unroll
    for (int o = 16; o; o >>= 1) s += __shfl_down_sync(0xffffffffu, s, o);
    if (lane == 0) g_edot[m * H + h] = s;
    if (threadIdx.x < MM) {
        int mm = threadIdx.x;
        float mu   = g_stats[mm * 4 + 0] * (1.f / EE);
        float var  = g_stats[mm * 4 + 1] * (1.f / EE) - mu * mu;
        float sc   = gamma[mm] * rsqrtf(var + 1e-5f);
        g_stats[mm * 4 + 2] = sc;
        g_stats[mm * 4 + 3] = beta[mm] - mu * sc;
    }
}

// ---------------- SGEMM + fused attention-dot epilogue ----------------
template<int K, int NC, int CT, int H>
__global__ void k_sgemm(const float* __restrict__ X, const float* __restrict__ Wall,
                        const float* __restrict__ asw, const float* __restrict__ adw) {
    constexpr int CP = CT / 16;
    constexpr int RW = 64 / CP;
    extern __shared__ float sm[];
    float* Xs = sm;                  // [64][68]
    float* Ws = sm + 64 * 68;        // [64][CT]
    int m = blockIdx.z;
    const float* W = Wall + (size_t)m * K * NC;
    float* Hd = g_h + (size_t)m * NN * NC;
    int nb = blockIdx.y * 64, cb = blockIdx.x * CT;
    int tid = threadIdx.x, tx = tid & 15, ty = tid >> 4;
    float acc[4][CP];
#pragma unroll
    for (int i = 0; i < 4; i++)
#pragma unroll
        for (int j = 0; j < CP; j++) acc[i][j] = 0.f;

    for (int kt = 0; kt < K; kt += 64) {
#pragma unroll
        for (int i = 0; i < 4; i++) {
            int v = tid + i * 256;
            int row = v >> 4, kq = (v & 15) << 2;
            int gr = nb + row;
            float4 xv = make_float4(0.f, 0.f, 0.f, 0.f);
            if (gr < NN) xv = *(const float4*)(X + (size_t)gr * K + kt + kq);
            *(float4*)&Xs[row * 68 + kq] = xv;
        }
#pragma unroll
        for (int i = 0; i < CP; i++) {
            int v = tid + i * 256;
            int krow = v / (CT / 4), cq = (v % (CT / 4)) * 4;
            *(float4*)&Ws[krow * CT + cq] = *(const float4*)(W + (size_t)(kt + krow) * NC + cb + cq);
        }
        __syncthreads();
#pragma unroll 8
        for (int k = 0; k < 64; k++) {
            float a[4];
#pragma unroll
            for (int i = 0; i < 4; i++) a[i] = Xs[(ty * 4 + i) * 68 + k];
            float b[CP];
#pragma unroll
            for (int jj = 0; jj < CP / 4; jj++) {
                float4 bv = *(float4*)&Ws[k * CT + tx * CP + 4 * jj];
                b[4 * jj + 0] = bv.x; b[4 * jj + 1] = bv.y;
                b[4 * jj + 2] = bv.z; b[4 * jj + 3] = bv.w;
            }
#pragma unroll
            for (int i = 0; i < 4; i++)
#pragma unroll
                for (int j = 0; j < CP; j++) acc[i][j] += a[i] * b[j];
        }
        __syncthreads();
    }
#pragma unroll
    for (int i = 0; i < 4; i++) {
        int gr = nb + ty * 4 + i;
        if (gr < NN) {
#pragma unroll
            for (int jj = 0; jj < CP / 4; jj++)
                *(float4*)(Hd + (size_t)gr * NC + cb + tx * CP + 4 * jj) =
                    make_float4(acc[i][4 * jj], acc[i][4 * jj + 1], acc[i][4 * jj + 2], acc[i][4 * jj + 3]);
        }
    }
    int colbase = cb + tx * CP;
    int head = colbase / 64;
#pragma unroll
    for (int i = 0; i < 4; i++) {
        float ps = 0.f, pd = 0.f;
#pragma unroll
        for (int j = 0; j < CP; j++) {
            ps += acc[i][j] * asw[m * H * 64 + colbase + j];
            pd += acc[i][j] * adw[m * H * 64 + colbase + j];
        }
#pragma unroll
        for (int off = RW / 2; off; off >>= 1) {
            ps += __shfl_down_sync(0xffffffffu, ps, off, RW);
            pd += __shfl_down_sync(0xffffffffu, pd, off, RW);
        }
        int gr = nb + ty * 4 + i;
        if ((tx & (RW - 1)) == 0 && gr < NN) {
            g_asrc[(size_t)(m * NN + gr) * H + head] = ps;
            g_adst[(size_t)(m * NN + gr) * H + head] = pd;
        }
    }
}

// ---------------- fused GAT (single-pass, unnormalized accumulate) ----------------
// thread = 4 channels (float4); TPN = H*C/4 threads per node; NPB nodes per 256-thread block.
// acc = sum_e ex_e * h[src_e],  den = sum_e ex_e,  out = acc/den (divide once at end).
template<int H, int C>
__global__ void k_gat(const float* __restrict__ bias) {
    constexpr int HC = H * C;
    constexpr int TPN = HC / 4;        // 64 (H=4) or 16 (H=1)
    constexpr int NPB = 256 / TPN;     // 4 or 16
    __shared__ float s_w[NPB][64 * H];
    __shared__ int   s_soff[NPB][64];
    __shared__ int   s_deg[NPB];
    __shared__ float s_acc[NPB][(H > 1) ? HC : 4];
    int tid = threadIdx.x;
    int g = tid / TPN, l = tid - g * TPN;
    int m = blockIdx.y;
    int n = blockIdx.x * NPB + g;
    bool valid = n < NN;
    int base = 0, deg = 0;
    if (valid) {
        base = g_rowptr[m * (NN + 1) + n];
        deg  = g_rowptr[m * (NN + 1) + n + 1] - base;
    }
    if (l == 0) s_deg[g] = deg;
    __syncthreads();
    int degmax = 0;
#pragma unroll
    for (int i = 0; i < NPB; i++) degmax = max(degmax, s_deg[i]);

    float sc = g_stats[m * 4 + 2], sh = g_stats[m * 4 + 3];
    float adst0 = 0.f; float4 adst4 = make_float4(0.f, 0.f, 0.f, 0.f);
    float edot0 = g_edot[m * H]; float4 edot4 = make_float4(0.f, 0.f, 0.f, 0.f);
    if (H == 4) {
        edot4 = *(const float4*)&g_edot[m * 4];
        if (valid) adst4 = *(const float4*)&g_adst[(size_t)(m * NN + n) * 4];
    } else {
        if (valid) adst0 = g_adst[m * NN + n];
    }

    const float4* hb4 = (const float4*)(g_h + (size_t)m * NN * HC);
    const int*   srcp = g_src + (size_t)m * EE + base;
    const float* leap = g_cea + (size_t)m * EE + base;
    int h = (H == 4) ? (l >> 4) : 0;
    float4 acc = make_float4(0.f, 0.f, 0.f, 0.f);
    float den = 0.f;

    for (int cs = 0; cs < degmax; cs += 64) {
        int cn = min(64, deg - cs);      // may be <=0 for finished groups
        // fill: one edge per pass-thread
        for (int j = l; j < cn; j += TPN) {
            int src = srcp[cs + j];
            float ea = leap[cs + j] * sc + sh;
            s_soff[g][j] = src * TPN;
            if (H == 4) {
                float4 as = *(const float4*)&g_asrc[(size_t)(m * NN + src) * 4];
                float4 wv;
                wv.x = lrelu_exp(as.x + adst4.x + ea * edot4.x);
                wv.y = lrelu_exp(as.y + adst4.y + ea * edot4.y);
                wv.z = lrelu_exp(as.z + adst4.z + ea * edot4.z);
                wv.w = lrelu_exp(as.w + adst4.w + ea * edot4.w);
                *(float4*)&s_w[g][j * 4] = wv;
            } else {
                s_w[g][j] = lrelu_exp(g_asrc[m * NN + src] + adst0 + ea * edot0);
            }
        }
        __syncthreads();
#pragma unroll 4
        for (int j = 0; j < cn; j++) {
            float w = s_w[g][j * H + h];
            float4 hv = hb4[s_soff[g][j] + l];
            den   += w;
            acc.x += w * hv.x; acc.y += w * hv.y;
            acc.z += w * hv.z; acc.w += w * hv.w;
        }
        __syncthreads();
    }

    float inv = 1.f / (den + 1e-16f);
    acc.x *= inv; acc.y *= inv; acc.z *= inv; acc.w *= inv;

    if (H == 1) {
        if (valid) {
            const float* bp = bias + m * C + 4 * l;
            float4 r;
            r.x = elu1(acc.x + bp[0]); r.y = elu1(acc.y + bp[1]);
            r.z = elu1(acc.z + bp[2]); r.w = elu1(acc.w + bp[3]);
            *(float4*)&g_zstack[((size_t)n * MM + m) * C + 4 * l] = r;
        }
    } else {
        *(float4*)&s_acc[g][l * 4] = acc;   // layout: [head*64 + c]
        __syncthreads();
        if (l < 16 && valid) {
            float4 t = make_float4(0.f, 0.f, 0.f, 0.f);
#pragma unroll
            for (int hh = 0; hh < H; hh++) {
                float4 v = *(float4*)&s_acc[g][hh * 64 + 4 * l];
                t.x += v.x; t.y += v.y; t.z += v.z; t.w += v.w;
            }
            const float* bp = bias + m * C + 4 * l;
            float4 r;
            r.x = elu1(t.x * (1.f / H) + bp[0]);
            r.y = elu1(t.y * (1.f / H) + bp[1]);
            r.z = elu1(t.z * (1.f / H) + bp[2]);
            r.w = elu1(t.w * (1.f / H) + bp[3]);
            *(float4*)&g_zstack[((size_t)n * MM + m) * C + 4 * l] = r;
        }
    }
}

// ---------------- semantic attention over M (4 nodes per block) ----------------
__global__ void k_semantic(const float* __restrict__ semw, const float* __restrict__ semb,
                           const float* __restrict__ semv,
                           float* __restrict__ out, float* beta_out) {
    __shared__ float zsh[4][MM][CC];
    __shared__ float wred[4][2];
    __shared__ float ssc[4][MM];
    int g = threadIdx.x >> 6, c = threadIdx.x & 63;
    int n = blockIdx.x * 4 + g;
    bool ok = n < NN;
#pragma unroll
    for (int m = 0; m < MM; m++)
        zsh[g][m][c] = ok ? g_zstack[((size_t)n * MM + m) * CC + c] : 0.f;
    __syncthreads();
#pragma unroll
    for (int m = 0; m < MM; m++) {
        float acc = semb[c];
#pragma unroll 16
        for (int k = 0; k < CC; k++) acc += zsh[g][m][k] * semw[k * CC + c];
        float v = tanhf(acc) * semv[c];
#pragma unroll
        for (int o = 16; o; o >>= 1) v += __shfl_down_sync(0xffffffffu, v, o);
        if ((c & 31) == 0) wred[g][c >> 5] = v;
        __syncthreads();
        if (c == 0) ssc[g][m] = wred[g][0] + wred[g][1];
        __syncthreads();
    }
    if (c == 0) {
        float mx = fmaxf(ssc[g][0], fmaxf(ssc[g][1], ssc[g][2]));
        float e0 = expf(ssc[g][0] - mx), e1 = expf(ssc[g][1] - mx), e2 = expf(ssc[g][2] - mx);
        float inv = 1.f / (e0 + e1 + e2);
        ssc[g][0] = e0 * inv; ssc[g][1] = e1 * inv; ssc[g][2] = e2 * inv;
    }
    __syncthreads();
    if (ok) {
        out[(size_t)n * CC + c] = zsh[g][0][c] * ssc[g][0] + zsh[g][1][c] * ssc[g][1] + zsh[g][2][c] * ssc[g][2];
        if (beta_out != nullptr && c < MM) beta_out[n * MM + c] = ssc[g][c];
    }
}

// ---------------- tiled fused decoder ----------------
__global__ void k_decoder(const float* __restrict__ z,
                          const float* __restrict__ w1, const float* __restrict__ b1,
                          const float* __restrict__ w2, const float* __restrict__ b2,
                          float* __restrict__ xhat) {
    extern __shared__ float sm[];
    float* Ts  = sm;               // [64][65]
    float* Zs  = sm + 4160;        // [64][65]
    float* W1s = sm + 8320;        // [64][64]
    float* W2s = sm + 4160;        // [64][128], overlays phase-1 space
    int nb = blockIdx.x * 64;
    int tid = threadIdx.x;
    int tx = tid & 15, ty = tid >> 4;
#pragma unroll
    for (int i = 0; i < 4; i++) {
        int v = tid + i * 256;
        int row = v >> 4, kq = (v & 15) << 2;
        int gr = nb + row;
        float4 zv = make_float4(0.f, 0.f, 0.f, 0.f);
        if (gr < NN) zv = *(const float4*)(z + (size_t)gr * CC + kq);
        Zs[row * 65 + kq + 0] = zv.x; Zs[row * 65 + kq + 1] = zv.y;
        Zs[row * 65 + kq + 2] = zv.z; Zs[row * 65 + kq + 3] = zv.w;
        *(float4*)&W1s[row * 64 + kq] = *(const float4*)(w1 + row * CC + kq);
    }
    __syncthreads();
    {
        float acc[4][4];
#pragma unroll
        for (int j = 0; j < 4; j++) {
            float bv = b1[tx * 4 + j];
#pragma unroll
            for (int i = 0; i < 4; i++) acc[i][j] = bv;
        }
#pragma unroll 16
        for (int k = 0; k < 64; k++) {
            float a0 = Zs[(ty * 4 + 0) * 65 + k];
            float a1 = Zs[(ty * 4 + 1) * 65 + k];
            float a2 = Zs[(ty * 4 + 2) * 65 + k];
            float a3 = Zs[(ty * 4 + 3) * 65 + k];
            float4 b = *(float4*)&W1s[k * 64 + tx * 4];
            acc[0][0] += a0 * b.x; acc[0][1] += a0 * b.y; acc[0][2] += a0 * b.z; acc[0][3] += a0 * b.w;
            acc[1][0] += a1 * b.x; acc[1][1] += a1 * b.y; acc[1][2] += a1 * b.z; acc[1][3] += a1 * b.w;
            acc[2][0] += a2 * b.x; acc[2][1] += a2 * b.y; acc[2][2] += a2 * b.z; acc[2][3] += a2 * b.w;
            acc[3][0] += a3 * b.x; acc[3][1] += a3 * b.y; acc[3][2] += a3 * b.z; acc[3][3] += a3 * b.w;
        }
#pragma unroll
        for (int i = 0; i < 4; i++)
#pragma unroll
            for (int j = 0; j < 4; j++)
                Ts[(ty * 4 + i) * 65 + tx * 4 + j] = elu1(acc[i][j]);
    }
    __syncthreads();
#pragma unroll
    for (int i = 0; i < 8; i++) {
        int v = tid + i * 256;
        int k = v >> 5, cq = (v & 31) << 2;
        *(float4*)&W2s[k * 128 + cq] = *(const float4*)(w2 + k * FIN + cq);
    }
    __syncthreads();
    {
        float acc[4][8];
#pragma unroll
        for (int j = 0; j < 4; j++) {
            float bva = b2[tx * 4 + j], bvb = b2[64 + tx * 4 + j];
#pragma unroll
            for (int i = 0; i < 4; i++) { acc[i][j] = bva; acc[i][j + 4] = bvb; }
        }
#pragma unroll 8
        for (int k = 0; k < 64; k++) {
            float a0 = Ts[(ty * 4 + 0) * 65 + k];
            float a1 = Ts[(ty * 4 + 1) * 65 + k];
            float a2 = Ts[(ty * 4 + 2) * 65 + k];
            float a3 = Ts[(ty * 4 + 3) * 65 + k];
            float4 ba = *(float4*)&W2s[k * 128 + tx * 4];
            float4 bb = *(float4*)&W2s[k * 128 + 64 + tx * 4];
            acc[0][0] += a0 * ba.x; acc[0][1] += a0 * ba.y; acc[0][2] += a0 * ba.z; acc[0][3] += a0 * ba.w;
            acc[1][0] += a1 * ba.x; acc[1][1] += a1 * ba.y; acc[1][2] += a1 * ba.z; acc[1][3] += a1 * ba.w;
            acc[2][0] += a2 * ba.x; acc[2][1] += a2 * ba.y; acc[2][2] += a2 * ba.z; acc[2][3] += a2 * ba.w;
            acc[3][0] += a3 * ba.x; acc[3][1] += a3 * ba.y; acc[3][2] += a3 * ba.z; acc[3][3] += a3 * ba.w;
            acc[0][4] += a0 * bb.x; acc[0][5] += a0 * bb.y; acc[0][6] += a0 * bb.z; acc[0][7] += a0 * bb.w;
            acc[1][4] += a1 * bb.x; acc[1][5] += a1 * bb.y; acc[1][6] += a1 * bb.z; acc[1][7] += a1 * bb.w;
            acc[2][4] += a2 * bb.x; acc[2][5] += a2 * bb.y; acc[2][6] += a2 * bb.z; acc[2][7] += a2 * bb.w;
            acc[3][4] += a3 * bb.x; acc[3][5] += a3 * bb.y; acc[3][6] += a3 * bb.z; acc[3][7] += a3 * bb.w;
        }
#pragma unroll
        for (int i = 0; i < 4; i++) {
            int gr = nb + ty * 4 + i;
            if (gr < NN) {
                *(float4*)(xhat + (size_t)gr * FIN + tx * 4) =
                    make_float4(acc[i][0], acc[i][1], acc[i][2], acc[i][3]);
                *(float4*)(xhat + (size_t)gr * FIN + 64 + tx * 4) =
                    make_float4(acc[i][4], acc[i][5], acc[i][6], acc[i][7]);
            }
        }
    }
}

// ---------------- host ----------------
extern "C" void kernel_launch(void* const* d_in, const int* in_sizes, int n_in,
                              void* d_out, int out_size) {
    const float* x      = (const float*)d_in[0];
    const int*   ei     = (const int*)  d_in[1];   // [M,2,E]
    const float* eattr  = (const float*)d_in[2];   // [M,E,1]
    const float* lin1w  = (const float*)d_in[3];
    const float* a1s    = (const float*)d_in[4];
    const float* a1d    = (const float*)d_in[5];
    const float* l1e    = (const float*)d_in[6];
    const float* a1e    = (const float*)d_in[7];
    const float* b1     = (const float*)d_in[8];
    const float* bn1g   = (const float*)d_in[9];
    const float* bn1b   = (const float*)d_in[10];
    const float* sem1w  = (const float*)d_in[11];
    const float* sem1b  = (const float*)d_in[12];
    const float* sem1v  = (const float*)d_in[13];
    const float* lin2w  = (const float*)d_in[14];
    const float* a2s    = (const float*)d_in[15];
    const float* a2d    = (const float*)d_in[16];
    const float* l2e    = (const float*)d_in[17];
    const float* a2e    = (const float*)d_in[18];
    const float* b2     = (const float*)d_in[19];
    const float* bn2g   = (const float*)d_in[20];
    const float* bn2b   = (const float*)d_in[21];
    const float* sem2w  = (const float*)d_in[22];
    const float* sem2b  = (const float*)d_in[23];
    const float* sem2v  = (const float*)d_in[24];
    const float* dec1w  = (const float*)d_in[25];
    const float* dec1b  = (const float*)d_in[26];
    const float* dec2w  = (const float*)d_in[27];
    const float* dec2b  = (const float*)d_in[28];

    float* z_out    = (float*)d_out;             // [N, C2]
    float* xhat     = z_out + NN * CC;           // [N, IN]
    float* beta_out = xhat + NN * FIN;           // [N, M]

    float* houtp = nullptr;
    cudaGetSymbolAddress((void**)&houtp, g_hout);

    const int EB = (EE + 255) / 256;
    const int NB64 = (NN + 63) / 64;

    int smem1 = (64 * 68 + 64 * 128) * 4;   // 50176
    int smem2 = (64 * 68 + 64 * 64) * 4;    // 33792
    cudaFuncSetAttribute(k_sgemm<FIN, HH * CC, 128, HH>, cudaFuncAttributeMaxDynamicSharedMemorySize, smem1);
    cudaFuncSetAttribute(k_sgemm<CC, CC, 64, 1>, cudaFuncAttributeMaxDynamicSharedMemorySize, smem2);
    cudaFuncSetAttribute(k_decoder, cudaFuncAttributeMaxDynamicSharedMemorySize, 12416 * 4);

    // ---- CSR build (shared by both layers) + BN stats ----
    k_zero1<<<(MM * NN + 255) / 256, 256>>>();
    k_build<<<dim3(EB, MM), 256>>>(ei, eattr);
    k_scan<<<MM, 1024>>>();
    k_scatter<<<dim3(EB, MM), 256>>>(ei);

    // ---- HAN layer 1 (heads = 4) ----
    k_bnfin<HH, CC><<<1, MM * HH * 32>>>(l1e, a1e, bn1g, bn1b);
    k_sgemm<FIN, HH * CC, 128, HH><<<dim3(2, NB64, MM), 256, smem1>>>(x, lin1w, a1s, a1d);
    k_gat<HH, CC><<<dim3((NN + 3) / 4, MM), 256>>>(b1);
    k_semantic<<<(NN + 3) / 4, 256>>>(sem1w, sem1b, sem1v, houtp, nullptr);

    // ---- HAN layer 2 (heads = 1) ----
    k_bnfin<1, CC><<<1, MM * 32>>>(l2e, a2e, bn2g, bn2b);
    k_sgemm<CC, CC, 64, 1><<<dim3(1, NB64, MM), 256, smem2>>>(houtp, lin2w, a2s, a2d);
    k_gat<1, CC><<<dim3((NN + 15) / 16, MM), 256>>>(b2);
    k_semantic<<<(NN + 3) / 4, 256>>>(sem2w, sem2b, sem2v, z_out, beta_out);

    // ---- decoder ----
    k_decoder<<<NB64, 256, 12416 * 4>>>(z_out, dec1w, dec1b, dec2w, dec2b, xhat);
}

// round 12
// speedup vs baseline: 2.6923x; 1.0647x over previous
#include <cuda_runtime.h>
#include <math.h>
#include <float.h>

#define NN 20000
#define EE 320000
#define MM 3
#define FIN 128
#define HH 4
#define CC 64
#define NEG_SLOPE 0.2f

// ---------------- scratch (device globals) ----------------
__device__ __align__(16) float g_h[MM * NN * HH * CC];     // projected features (fp32)
__device__ __align__(16) float g_asrc[MM * NN * HH];
__device__ __align__(16) float g_adst[MM * NN * HH];
__device__ __align__(16) float g_zstack[NN * MM * CC];
__device__ __align__(16) float g_hout[NN * CC];
__device__ float g_stats[MM * 2];                           // per m: sum, sumsq (raw only)
__device__ __align__(16) float g_edot1[MM * HH];            // layer-1 per-head edge scalars
__device__ float g_edot2[MM];                               // layer-2 edge scalars
__device__ float g_aff1[MM * 2];                            // layer-1 BN scale/shift
__device__ float g_aff2[MM * 2];                            // layer-2 BN scale/shift
// CSR: payload packed {src, log1p(attr)} in CSR order
__device__ int   g_deg[MM * NN];
__device__ int   g_rowptr[MM * (NN + 1)];
__device__ int   g_cursor[MM * NN];
__device__ float g_lea[MM * EE];                            // log1p(attr), edge order
__device__ __align__(8) int2 g_sl[MM * EE];                 // {src, bitcast lea}, CSR order

// ---------------- helpers ----------------
__device__ __forceinline__ float elu1(float x) { return x > 0.f ? x : expm1f(x); }
__device__ __forceinline__ float lrelu_exp(float a) {
    a = a > 0.f ? a : NEG_SLOPE * a;
    return expf(a);
}

// ---------------- zero init ----------------
__global__ void k_zero1() {
    int i = blockIdx.x * blockDim.x + threadIdx.x;
    if (i < MM * NN) g_deg[i] = 0;
    if (i < MM * 2) g_stats[i] = 0.f;
}

// ---------------- fused: degree histogram + log1p + BN stats ----------------
__global__ void k_build(const int* __restrict__ ei_all, const float* __restrict__ attr) {
    int m = blockIdx.y;
    int e = blockIdx.x * 256 + threadIdx.x;
    float v = 0.f, v2 = 0.f;
    if (e < EE) {
        atomicAdd(&g_deg[m * NN + ei_all[m * 2 * EE + EE + e]], 1);
        float t = log1pf(attr[m * EE + e]);
        g_lea[(size_t)m * EE + e] = t;
        v = t; v2 = t * t;
    }
#pragma unroll
    for (int o = 16; o; o >>= 1) {
        v  += __shfl_down_sync(0xffffffffu, v,  o);
        v2 += __shfl_down_sync(0xffffffffu, v2, o);
    }
    __shared__ float s1[8], s2[8];
    int lane = threadIdx.x & 31, w = threadIdx.x >> 5;
    if (lane == 0) { s1[w] = v; s2[w] = v2; }
    __syncthreads();
    if (threadIdx.x == 0) {
        float a = 0.f, b = 0.f;
        for (int j = 0; j < 8; j++) { a += s1[j]; b += s2[j]; }
        atomicAdd(&g_stats[m * 2 + 0], a);
        atomicAdd(&g_stats[m * 2 + 1], b);
    }
}

// ---------------- CSR: exclusive scan (one block per metapath) ----------------
__global__ void k_scan() {
    int m = blockIdx.x;
    __shared__ int swarp[32];
    int tid = threadIdx.x, lane = tid & 31, w = tid >> 5;
    int carry = 0;
    if (tid == 0) g_rowptr[m * (NN + 1)] = 0;
    for (int c0 = 0; c0 < NN; c0 += 1024) {
        int i = c0 + tid;
        int v = (i < NN) ? g_deg[m * NN + i] : 0;
        int incl = v;
#pragma unroll
        for (int off = 1; off < 32; off <<= 1) {
            int t = __shfl_up_sync(0xffffffffu, incl, off);
            if (lane >= off) incl += t;
        }
        if (lane == 31) swarp[w] = incl;
        __syncthreads();
        if (w == 0) {
            int x = swarp[lane];
#pragma unroll
            for (int off = 1; off < 32; off <<= 1) {
                int t = __shfl_up_sync(0xffffffffu, x, off);
                if (lane >= off) x += t;
            }
            swarp[lane] = x;
        }
        __syncthreads();
        int offset = (w > 0) ? swarp[w - 1] : 0;
        int total = swarp[31];
        incl += offset;
        if (i < NN) {
            g_rowptr[m * (NN + 1) + i + 1] = carry + incl;
            g_cursor[m * NN + i] = carry + incl - v;
        }
        carry += total;
        __syncthreads();
    }
}

// ---------------- CSR: scatter packed payload ----------------
__global__ void k_scatter(const int* __restrict__ ei_all) {
    int e = blockIdx.x * 256 + threadIdx.x;
    if (e >= EE) return;
    int m = blockIdx.y;
    int s = ei_all[m * 2 * EE + e];
    int d = ei_all[m * 2 * EE + EE + e];
    int pos = atomicAdd(&g_cursor[m * NN + d], 1);
    g_sl[(size_t)m * EE + pos] = make_int2(s, __float_as_int(g_lea[(size_t)m * EE + e]));
}

// ---------------- finalize BN affine + per-head edge scalar (de-aliased) -------
template<int H, int C>
__global__ void k_bnfin(const float* __restrict__ lew, const float* __restrict__ aew,
                        const float* __restrict__ gamma, const float* __restrict__ beta,
                        float* __restrict__ edot_out, float* __restrict__ aff_out) {
    int w = threadIdx.x >> 5, lane = threadIdx.x & 31;   // MM*H warps
    int m = w / H, h = w % H;
    float s = 0.f;
    for (int c = lane; c < C; c += 32)
        s += lew[(m * H + h) * C + c] * aew[(m * H + h) * C + c];
#pragma unroll
    for (int o = 16; o; o >>= 1) s += __shfl_down_sync(0xffffffffu, s, o);
    if (lane == 0) edot_out[m * H + h] = s;
    if (threadIdx.x < MM) {
        int mm = threadIdx.x;
        float mu   = g_stats[mm * 2 + 0] * (1.f / EE);
        float var  = g_stats[mm * 2 + 1] * (1.f / EE) - mu * mu;
        float sc   = gamma[mm] * rsqrtf(var + 1e-5f);
        aff_out[mm * 2 + 0] = sc;
        aff_out[mm * 2 + 1] = beta[mm] - mu * sc;
    }
}

// ---------------- SGEMM + fused attention-dot epilogue ----------------
template<int K, int NC, int CT, int H>
__global__ void k_sgemm(const float* __restrict__ X, const float* __restrict__ Wall,
                        const float* __restrict__ asw, const float* __restrict__ adw) {
    constexpr int CP = CT / 16;
    constexpr int RW = 64 / CP;
    extern __shared__ float sm[];
    float* Xs = sm;                  // [64][68]
    float* Ws = sm + 64 * 68;        // [64][CT]
    int m = blockIdx.z;
    const float* W = Wall + (size_t)m * K * NC;
    float* Hd = g_h + (size_t)m * NN * NC;
    int nb = blockIdx.y * 64, cb = blockIdx.x * CT;
    int tid = threadIdx.x, tx = tid & 15, ty = tid >> 4;
    float acc[4][CP];
#pragma unroll
    for (int i = 0; i < 4; i++)
#pragma unroll
        for (int j = 0; j < CP; j++) acc[i][j] = 0.f;

    for (int kt = 0; kt < K; kt += 64) {
#pragma unroll
        for (int i = 0; i < 4; i++) {
            int v = tid + i * 256;
            int row = v >> 4, kq = (v & 15) << 2;
            int gr = nb + row;
            float4 xv = make_float4(0.f, 0.f, 0.f, 0.f);
            if (gr < NN) xv = *(const float4*)(X + (size_t)gr * K + kt + kq);
            *(float4*)&Xs[row * 68 + kq] = xv;
        }
#pragma unroll
        for (int i = 0; i < CP; i++) {
            int v = tid + i * 256;
            int krow = v / (CT / 4), cq = (v % (CT / 4)) * 4;
            *(float4*)&Ws[krow * CT + cq] = *(const float4*)(W + (size_t)(kt + krow) * NC + cb + cq);
        }
        __syncthreads();
#pragma unroll 8
        for (int k = 0; k < 64; k++) {
            float a[4];
#pragma unroll
            for (int i = 0; i < 4; i++) a[i] = Xs[(ty * 4 + i) * 68 + k];
            float b[CP];
#pragma unroll
            for (int jj = 0; jj < CP / 4; jj++) {
                float4 bv = *(float4*)&Ws[k * CT + tx * CP + 4 * jj];
                b[4 * jj + 0] = bv.x; b[4 * jj + 1] = bv.y;
                b[4 * jj + 2] = bv.z; b[4 * jj + 3] = bv.w;
            }
#pragma unroll
            for (int i = 0; i < 4; i++)
#pragma unroll
                for (int j = 0; j < CP; j++) acc[i][j] += a[i] * b[j];
        }
        __syncthreads();
    }
#pragma unroll
    for (int i = 0; i < 4; i++) {
        int gr = nb + ty * 4 + i;
        if (gr < NN) {
#pragma unroll
            for (int jj = 0; jj < CP / 4; jj++)
                *(float4*)(Hd + (size_t)gr * NC + cb + tx * CP + 4 * jj) =
                    make_float4(acc[i][4 * jj], acc[i][4 * jj + 1], acc[i][4 * jj + 2], acc[i][4 * jj + 3]);
        }
    }
    // fused attention dots
    int colbase = cb + tx * CP;
    int head = colbase / 64;
#pragma unroll
    for (int i = 0; i < 4; i++) {
        float ps = 0.f, pd = 0.f;
#pragma unroll
        for (int j = 0; j < CP; j++) {
            ps += acc[i][j] * asw[m * H * 64 + colbase + j];
            pd += acc[i][j] * adw[m * H * 64 + colbase + j];
        }
#pragma unroll
        for (int off = RW / 2; off; off >>= 1) {
            ps += __shfl_down_sync(0xffffffffu, ps, off, RW);
            pd += __shfl_down_sync(0xffffffffu, pd, off, RW);
        }
        int gr = nb + ty * 4 + i;
        if ((tx & (RW - 1)) == 0 && gr < NN) {
            g_asrc[(size_t)(m * NN + gr) * H + head] = ps;
            g_adst[(size_t)(m * NN + gr) * H + head] = pd;
        }
    }
}

// ---------------- GAT layer 1 (H=4): one warp per node, fp32 ----------------
// lane l owns float4 q=l (heads 0/1 region) and q=l+32 (heads 2/3 region).
// per-head unnormalized accumulate; divide per head; head-mean via shfl_down(16).
__global__ void k_gat4(const float* __restrict__ bias) {
    __shared__ float s_w[8][64 * 4];
    __shared__ int   s_soff[8][64];
    int w = threadIdx.x >> 5, l = threadIdx.x & 31;
    int m = blockIdx.y;
    int n = blockIdx.x * 8 + w;                 // grid.x = NN/8 exact
    int base = g_rowptr[m * (NN + 1) + n];
    int deg  = g_rowptr[m * (NN + 1) + n + 1] - base;
    float sc = g_aff1[m * 2 + 0], sh = g_aff1[m * 2 + 1];
    float4 edot = *(const float4*)&g_edot1[m * 4];
    float4 adst = *(const float4*)&g_adst[(size_t)(m * NN + n) * 4];
    const int2* slp = g_sl + (size_t)m * EE + base;
    const float4* hb = (const float4*)(g_h + (size_t)m * NN * 256);   // 64 float4/node
    int h0 = l >> 4;                            // 0 or 1; second accum uses h0+2
    float4 acc0 = make_float4(0.f, 0.f, 0.f, 0.f);
    float4 acc1 = make_float4(0.f, 0.f, 0.f, 0.f);
    float den0 = 0.f, den1 = 0.f;

    for (int cs = 0; cs < deg; cs += 64) {
        int cn = min(64, deg - cs);
        for (int j = l; j < cn; j += 32) {
            int2 sl = slp[cs + j];
            float ea = __int_as_float(sl.y) * sc + sh;
            float4 as = *(const float4*)&g_asrc[(size_t)(m * NN + sl.x) * 4];
            s_soff[w][j] = sl.x * 64;
            float4 wv;
            wv.x = lrelu_exp(as.x + adst.x + ea * edot.x);
            wv.y = lrelu_exp(as.y + adst.y + ea * edot.y);
            wv.z = lrelu_exp(as.z + adst.z + ea * edot.z);
            wv.w = lrelu_exp(as.w + adst.w + ea * edot.w);
            *(float4*)&s_w[w][j * 4] = wv;
        }
        __syncwarp();
#pragma unroll 2
        for (int j = 0; j < cn; j++) {
            float w0 = s_w[w][j * 4 + h0];
            float w2 = s_w[w][j * 4 + h0 + 2];
            int so = s_soff[w][j];
            float4 v0 = hb[so + l];
            float4 v1 = hb[so + 32 + l];
            acc0.x += w0 * v0.x; acc0.y += w0 * v0.y; acc0.z += w0 * v0.z; acc0.w += w0 * v0.w;
            acc1.x += w2 * v1.x; acc1.y += w2 * v1.y; acc1.z += w2 * v1.z; acc1.w += w2 * v1.w;
            den0 += w0; den1 += w2;
        }
        __syncwarp();
    }

    float i0 = 1.f / (den0 + 1e-16f);
    float i1 = 1.f / (den1 + 1e-16f);
    // per-head normalize, then sum the two heads this lane owns
    float4 loc;
    loc.x = acc0.x * i0 + acc1.x * i1;
    loc.y = acc0.y * i0 + acc1.y * i1;
    loc.z = acc0.z * i0 + acc1.z * i1;
    loc.w = acc0.w * i0 + acc1.w * i1;
    // add heads from lane l+16 (other head parity, same channel offsets)
    loc.x += __shfl_down_sync(0xffffffffu, loc.x, 16);
    loc.y += __shfl_down_sync(0xffffffffu, loc.y, 16);
    loc.z += __shfl_down_sync(0xffffffffu, loc.z, 16);
    loc.w += __shfl_down_sync(0xffffffffu, loc.w, 16);
    if (l < 16) {
        const float* bp = bias + m * 64 + 4 * l;
        float4 r;
        r.x = elu1(loc.x * 0.25f + bp[0]);
        r.y = elu1(loc.y * 0.25f + bp[1]);
        r.z = elu1(loc.z * 0.25f + bp[2]);
        r.w = elu1(loc.w * 0.25f + bp[3]);
        *(float4*)&g_zstack[((size_t)n * MM + m) * 64 + 4 * l] = r;
    }
}

// ---------------- GAT layer 2 (H=1): 8 lanes/node, fp32, no smem/syncs --------
__global__ void k_gat1(const float* __restrict__ bias) {
    int tid = threadIdx.x;
    int g = tid >> 3, l8 = tid & 7;
    int m = blockIdx.y;
    int n = blockIdx.x * 32 + g;                // grid.x = NN/32 exact
    int base = g_rowptr[m * (NN + 1) + n];
    int deg  = g_rowptr[m * (NN + 1) + n + 1] - base;
    float sc = g_aff2[m * 2 + 0], sh = g_aff2[m * 2 + 1];
    float edot = g_edot2[m];
    float adst = g_adst[m * NN + n];
    const int2* slp = g_sl + (size_t)m * EE + base;
    const float4* hb = (const float4*)(g_h + (size_t)m * NN * 64);    // 16 float4/node
    const float* asp = g_asrc + (size_t)m * NN;
    float4 acc0 = make_float4(0.f, 0.f, 0.f, 0.f);
    float4 acc1 = make_float4(0.f, 0.f, 0.f, 0.f);
    float den = 0.f;

    for (int j = 0; j < deg; j++) {
        int2 sl = slp[j];
        float ea = __int_as_float(sl.y) * sc + sh;
        float wt = lrelu_exp(asp[sl.x] + adst + ea * edot);
        int so = sl.x * 16;
        float4 v0 = hb[so + l8];
        float4 v1 = hb[so + 8 + l8];
        acc0.x += wt * v0.x; acc0.y += wt * v0.y; acc0.z += wt * v0.z; acc0.w += wt * v0.w;
        acc1.x += wt * v1.x; acc1.y += wt * v1.y; acc1.z += wt * v1.z; acc1.w += wt * v1.w;
        den += wt;
    }
    float inv = 1.f / (den + 1e-16f);
    const float* bp = bias + m * 64;
    float4 r0, r1;
    r0.x = elu1(acc0.x * inv + bp[4 * l8 + 0]);
    r0.y = elu1(acc0.y * inv + bp[4 * l8 + 1]);
    r0.z = elu1(acc0.z * inv + bp[4 * l8 + 2]);
    r0.w = elu1(acc0.w * inv + bp[4 * l8 + 3]);
    r1.x = elu1(acc1.x * inv + bp[32 + 4 * l8 + 0]);
    r1.y = elu1(acc1.y * inv + bp[32 + 4 * l8 + 1]);
    r1.z = elu1(acc1.z * inv + bp[32 + 4 * l8 + 2]);
    r1.w = elu1(acc1.w * inv + bp[32 + 4 * l8 + 3]);
    float* zp = &g_zstack[((size_t)n * MM + m) * 64];
    *(float4*)(zp + 4 * l8) = r0;
    *(float4*)(zp + 32 + 4 * l8) = r1;
}

// ---------------- semantic attention over M (4 nodes per block) ----------------
__global__ void k_semantic(const float* __restrict__ semw, const float* __restrict__ semb,
                           const float* __restrict__ semv,
                           float* __restrict__ out, float* beta_out) {
    __shared__ float zsh[4][MM][CC];
    __shared__ float wred[4][2];
    __shared__ float ssc[4][MM];
    int g = threadIdx.x >> 6, c = threadIdx.x & 63;
    int n = blockIdx.x * 4 + g;
    bool ok = n < NN;
#pragma unroll
    for (int m = 0; m < MM; m++)
        zsh[g][m][c] = ok ? g_zstack[((size_t)n * MM + m) * CC + c] : 0.f;
    __syncthreads();
#pragma unroll
    for (int m = 0; m < MM; m++) {
        float acc = semb[c];
#pragma unroll 16
        for (int k = 0; k < CC; k++) acc += zsh[g][m][k] * semw[k * CC + c];
        float v = tanhf(acc) * semv[c];
#pragma unroll
        for (int o = 16; o; o >>= 1) v += __shfl_down_sync(0xffffffffu, v, o);
        if ((c & 31) == 0) wred[g][c >> 5] = v;
        __syncthreads();
        if (c == 0) ssc[g][m] = wred[g][0] + wred[g][1];
        __syncthreads();
    }
    if (c == 0) {
        float mx = fmaxf(ssc[g][0], fmaxf(ssc[g][1], ssc[g][2]));
        float e0 = expf(ssc[g][0] - mx), e1 = expf(ssc[g][1] - mx), e2 = expf(ssc[g][2] - mx);
        float inv = 1.f / (e0 + e1 + e2);
        ssc[g][0] = e0 * inv; ssc[g][1] = e1 * inv; ssc[g][2] = e2 * inv;
    }
    __syncthreads();
    if (ok) {
        out[(size_t)n * CC + c] = zsh[g][0][c] * ssc[g][0] + zsh[g][1][c] * ssc[g][1] + zsh[g][2][c] * ssc[g][2];
        if (beta_out != nullptr && c < MM) beta_out[n * MM + c] = ssc[g][c];
    }
}

// ---------------- tiled fused decoder ----------------
__global__ void k_decoder(const float* __restrict__ z,
                          const float* __restrict__ w1, const float* __restrict__ b1,
                          const float* __restrict__ w2, const float* __restrict__ b2,
                          float* __restrict__ xhat) {
    extern __shared__ float sm[];
    float* Ts  = sm;               // [64][65]
    float* Zs  = sm + 4160;        // [64][65]
    float* W1s = sm + 8320;        // [64][64]
    float* W2s = sm + 4160;        // [64][128], overlays phase-1 space
    int nb = blockIdx.x * 64;
    int tid = threadIdx.x;
    int tx = tid & 15, ty = tid >> 4;
#pragma unroll
    for (int i = 0; i < 4; i++) {
        int v = tid + i * 256;
        int row = v >> 4, kq = (v & 15) << 2;
        int gr = nb + row;
        float4 zv = make_float4(0.f, 0.f, 0.f, 0.f);
        if (gr < NN) zv = *(const float4*)(z + (size_t)gr * CC + kq);
        Zs[row * 65 + kq + 0] = zv.x; Zs[row * 65 + kq + 1] = zv.y;
        Zs[row * 65 + kq + 2] = zv.z; Zs[row * 65 + kq + 3] = zv.w;
        *(float4*)&W1s[row * 64 + kq] = *(const float4*)(w1 + row * CC + kq);
    }
    __syncthreads();
    {
        float acc[4][4];
#pragma unroll
        for (int j = 0; j < 4; j++) {
            float bv = b1[tx * 4 + j];
#pragma unroll
            for (int i = 0; i < 4; i++) acc[i][j] = bv;
        }
#pragma unroll 16
        for (int k = 0; k < 64; k++) {
            float a0 = Zs[(ty * 4 + 0) * 65 + k];
            float a1 = Zs[(ty * 4 + 1) * 65 + k];
            float a2 = Zs[(ty * 4 + 2) * 65 + k];
            float a3 = Zs[(ty * 4 + 3) * 65 + k];
            float4 b = *(float4*)&W1s[k * 64 + tx * 4];
            acc[0][0] += a0 * b.x; acc[0][1] += a0 * b.y; acc[0][2] += a0 * b.z; acc[0][3] += a0 * b.w;
            acc[1][0] += a1 * b.x; acc[1][1] += a1 * b.y; acc[1][2] += a1 * b.z; acc[1][3] += a1 * b.w;
            acc[2][0] += a2 * b.x; acc[2][1] += a2 * b.y; acc[2][2] += a2 * b.z; acc[2][3] += a2 * b.w;
            acc[3][0] += a3 * b.x; acc[3][1] += a3 * b.y; acc[3][2] += a3 * b.z; acc[3][3] += a3 * b.w;
        }
#pragma unroll
        for (int i = 0; i < 4; i++)
#pragma unroll
            for (int j = 0; j < 4; j++)
                Ts[(ty * 4 + i) * 65 + tx * 4 + j] = elu1(acc[i][j]);
    }
    __syncthreads();
#pragma unroll
    for (int i = 0; i < 8; i++) {
        int v = tid + i * 256;
        int k = v >> 5, cq = (v & 31) << 2;
        *(float4*)&W2s[k * 128 + cq] = *(const float4*)(w2 + k * FIN + cq);
    }
    __syncthreads();
    {
        float acc[4][8];
#pragma unroll
        for (int j = 0; j < 4; j++) {
            float bva = b2[tx * 4 + j], bvb = b2[64 + tx * 4 + j];
#pragma unroll
            for (int i = 0; i < 4; i++) { acc[i][j] = bva; acc[i][j + 4] = bvb; }
        }
#pragma unroll 8
        for (int k = 0; k < 64; k++) {
            float a0 = Ts[(ty * 4 + 0) * 65 + k];
            float a1 = Ts[(ty * 4 + 1) * 65 + k];
            float a2 = Ts[(ty * 4 + 2) * 65 + k];
            float a3 = Ts[(ty * 4 + 3) * 65 + k];
            float4 ba = *(float4*)&W2s[k * 128 + tx * 4];
            float4 bb = *(float4*)&W2s[k * 128 + 64 + tx * 4];
            acc[0][0] += a0 * ba.x; acc[0][1] += a0 * ba.y; acc[0][2] += a0 * ba.z; acc[0][3] += a0 * ba.w;
            acc[1][0] += a1 * ba.x; acc[1][1] += a1 * ba.y; acc[1][2] += a1 * ba.z; acc[1][3] += a1 * ba.w;
            acc[2][0] += a2 * ba.x; acc[2][1] += a2 * ba.y; acc[2][2] += a2 * ba.z; acc[2][3] += a2 * ba.w;
            acc[3][0] += a3 * ba.x; acc[3][1] += a3 * ba.y; acc[3][2] += a3 * ba.z; acc[3][3] += a3 * ba.w;
            acc[0][4] += a0 * bb.x; acc[0][5] += a0 * bb.y; acc[0][6] += a0 * bb.z; acc[0][7] += a0 * bb.w;
            acc[1][4] += a1 * bb.x; acc[1][5] += a1 * bb.y; acc[1][6] += a1 * bb.z; acc[1][7] += a1 * bb.w;
            acc[2][4] += a2 * bb.x; acc[2][5] += a2 * bb.y; acc[2][6] += a2 * bb.z; acc[2][7] += a2 * bb.w;
            acc[3][4] += a3 * bb.x; acc[3][5] += a3 * bb.y; acc[3][6] += a3 * bb.z; acc[3][7] += a3 * bb.w;
        }
#pragma unroll
        for (int i = 0; i < 4; i++) {
            int gr = nb + ty * 4 + i;
            if (gr < NN) {
                *(float4*)(xhat + (size_t)gr * FIN + tx * 4) =
                    make_float4(acc[i][0], acc[i][1], acc[i][2], acc[i][3]);
                *(float4*)(xhat + (size_t)gr * FIN + 64 + tx * 4) =
                    make_float4(acc[i][4], acc[i][5], acc[i][6], acc[i][7]);
            }
        }
    }
}

// ---------------- host (single stream — no fork) ----------------
extern "C" void kernel_launch(void* const* d_in, const int* in_sizes, int n_in,
                              void* d_out, int out_size) {
    const float* x      = (const float*)d_in[0];
    const int*   ei     = (const int*)  d_in[1];   // [M,2,E]
    const float* eattr  = (const float*)d_in[2];   // [M,E,1]
    const float* lin1w  = (const float*)d_in[3];
    const float* a1s    = (const float*)d_in[4];
    const float* a1d    = (const float*)d_in[5];
    const float* l1e    = (const float*)d_in[6];
    const float* a1e    = (const float*)d_in[7];
    const float* b1     = (const float*)d_in[8];
    const float* bn1g   = (const float*)d_in[9];
    const float* bn1b   = (const float*)d_in[10];
    const float* sem1w  = (const float*)d_in[11];
    const float* sem1b  = (const float*)d_in[12];
    const float* sem1v  = (const float*)d_in[13];
    const float* lin2w  = (const float*)d_in[14];
    const float* a2s    = (const float*)d_in[15];
    const float* a2d    = (const float*)d_in[16];
    const float* l2e    = (const float*)d_in[17];
    const float* a2e    = (const float*)d_in[18];
    const float* b2     = (const float*)d_in[19];
    const float* bn2g   = (const float*)d_in[20];
    const float* bn2b   = (const float*)d_in[21];
    const float* sem2w  = (const float*)d_in[22];
    const float* sem2b  = (const float*)d_in[23];
    const float* sem2v  = (const float*)d_in[24];
    const float* dec1w  = (const float*)d_in[25];
    const float* dec1b  = (const float*)d_in[26];
    const float* dec2w  = (const float*)d_in[27];
    const float* dec2b  = (const float*)d_in[28];

    float* z_out    = (float*)d_out;             // [N, C2]
    float* xhat     = z_out + NN * CC;           // [N, IN]
    float* beta_out = xhat + NN * FIN;           // [N, M]

    float* houtp = nullptr;
    cudaGetSymbolAddress((void**)&houtp, g_hout);
    float *edot1p = nullptr, *edot2p = nullptr, *aff1p = nullptr, *aff2p = nullptr;
    cudaGetSymbolAddress((void**)&edot1p, g_edot1);
    cudaGetSymbolAddress((void**)&edot2p, g_edot2);
    cudaGetSymbolAddress((void**)&aff1p, g_aff1);
    cudaGetSymbolAddress((void**)&aff2p, g_aff2);

    const int EB = (EE + 255) / 256;
    const int NB64 = (NN + 63) / 64;

    int smem1 = (64 * 68 + 64 * 128) * 4;   // 50176
    int smem2 = (64 * 68 + 64 * 64) * 4;    // 33792
    cudaFuncSetAttribute(k_sgemm<FIN, HH * CC, 128, HH>, cudaFuncAttributeMaxDynamicSharedMemorySize, smem1);
    cudaFuncSetAttribute(k_sgemm<CC, CC, 64, 1>, cudaFuncAttributeMaxDynamicSharedMemorySize, smem2);
    cudaFuncSetAttribute(k_decoder, cudaFuncAttributeMaxDynamicSharedMemorySize, 12416 * 4);

    // ---- CSR build (shared by both layers) + BN, serial ----
    k_zero1<<<(MM * NN + 255) / 256, 256>>>();
    k_build<<<dim3(EB, MM), 256>>>(ei, eattr);
    k_scan<<<MM, 1024>>>();
    k_scatter<<<dim3(EB, MM), 256>>>(ei);
    k_bnfin<HH, CC><<<1, MM * HH * 32>>>(l1e, a1e, bn1g, bn1b, edot1p, aff1p);
    k_bnfin<1, CC><<<1, MM * 32>>>(l2e, a2e, bn2g, bn2b, edot2p, aff2p);

    // ---- HAN layer 1 (heads = 4) ----
    k_sgemm<FIN, HH * CC, 128, HH><<<dim3(2, NB64, MM), 256, smem1>>>(x, lin1w, a1s, a1d);
    k_gat4<<<dim3(NN / 8, MM), 256>>>(b1);
    k_semantic<<<(NN + 3) / 4, 256>>>(sem1w, sem1b, sem1v, houtp, nullptr);

    // ---- HAN layer 2 (heads = 1) ----
    k_sgemm<CC, CC, 64, 1><<<dim3(1, NB64, MM), 256, smem2>>>(houtp, lin2w, a2s, a2d);
    k_gat1<<<dim3(NN / 32, MM), 256>>>(b2);
    k_semantic<<<(NN + 3) / 4, 256>>>(sem2w, sem2b, sem2v, z_out, beta_out);

    // ---- decoder ----
    k_decoder<<<NB64, 256, 12416 * 4>>>(z_out, dec1w, dec1b, dec2w, dec2b, xhat);
}

// round 13
// speedup vs baseline: 2.8701x; 1.0660x over previous
#include <cuda_runtime.h>
#include <cuda_fp16.h>
#include <math.h>
#include <float.h>

#define NN 20000
#define EE 320000
#define MM 3
#define FIN 128
#define HH 4
#define CC 64
#define NEG_SLOPE 0.2f

// ---------------- scratch (device globals) ----------------
__device__ __align__(16) __half g_h[MM * NN * HH * CC];    // projected features (fp16)
__device__ __align__(16) float g_asrc[MM * NN * HH];
__device__ __align__(16) float g_adst[MM * NN * HH];
__device__ __align__(16) float g_zstack[NN * MM * CC];
__device__ __align__(16) float g_hout[NN * CC];
__device__ float g_stats[MM * 2];                           // per m: sum, sumsq (raw only)
__device__ __align__(16) float g_edot1[MM * HH];            // layer-1 per-head edge scalars
__device__ float g_edot2[MM];                               // layer-2 edge scalars
__device__ float g_aff1[MM * 2];                            // layer-1 BN scale/shift
__device__ float g_aff2[MM * 2];                            // layer-2 BN scale/shift
// CSR: payload packed {src, log1p(attr)} in CSR order
__device__ int   g_deg[MM * NN];
__device__ int   g_rowptr[MM * (NN + 1)];
__device__ int   g_cursor[MM * NN];
__device__ float g_lea[MM * EE];                            // log1p(attr), edge order
__device__ __align__(8) int2 g_sl[MM * EE];                 // {src, bitcast lea}, CSR order

// ---------------- helpers ----------------
__device__ __forceinline__ float elu1(float x) { return x > 0.f ? x : expm1f(x); }
__device__ __forceinline__ float lrelu_exp(float a) {
    a = a > 0.f ? a : NEG_SLOPE * a;
    return expf(a);
}
__device__ __forceinline__ unsigned pack2(float a, float b) {
    __half2 h = __float22half2_rn(make_float2(a, b));
    return *(unsigned*)&h;
}
__device__ __forceinline__ float2 up2(unsigned u) {
    return __half22float2(*(__half2*)&u);
}

// ---------------- zero init ----------------
__global__ void k_zero1() {
    int i = blockIdx.x * blockDim.x + threadIdx.x;
    if (i < MM * NN) g_deg[i] = 0;
    if (i < MM * 2) g_stats[i] = 0.f;
}

// ---------------- fused: degree histogram + log1p + BN stats ----------------
__global__ void k_build(const int* __restrict__ ei_all, const float* __restrict__ attr) {
    int m = blockIdx.y;
    int e = blockIdx.x * 256 + threadIdx.x;
    float v = 0.f, v2 = 0.f;
    if (e < EE) {
        atomicAdd(&g_deg[m * NN + ei_all[m * 2 * EE + EE + e]], 1);
        float t = log1pf(attr[m * EE + e]);
        g_lea[(size_t)m * EE + e] = t;
        v = t; v2 = t * t;
    }
#pragma unroll
    for (int o = 16; o; o >>= 1) {
        v  += __shfl_down_sync(0xffffffffu, v,  o);
        v2 += __shfl_down_sync(0xffffffffu, v2, o);
    }
    __shared__ float s1[8], s2[8];
    int lane = threadIdx.x & 31, w = threadIdx.x >> 5;
    if (lane == 0) { s1[w] = v; s2[w] = v2; }
    __syncthreads();
    if (threadIdx.x == 0) {
        float a = 0.f, b = 0.f;
        for (int j = 0; j < 8; j++) { a += s1[j]; b += s2[j]; }
        atomicAdd(&g_stats[m * 2 + 0], a);
        atomicAdd(&g_stats[m * 2 + 1], b);
    }
}

// ---------------- CSR: exclusive scan (one block per metapath) ----------------
__global__ void k_scan() {
    int m = blockIdx.x;
    __shared__ int swarp[32];
    int tid = threadIdx.x, lane = tid & 31, w = tid >> 5;
    int carry = 0;
    if (tid == 0) g_rowptr[m * (NN + 1)] = 0;
    for (int c0 = 0; c0 < NN; c0 += 1024) {
        int i = c0 + tid;
        int v = (i < NN) ? g_deg[m * NN + i] : 0;
        int incl = v;
#pragma unroll
        for (int off = 1; off < 32; off <<= 1) {
            int t = __shfl_up_sync(0xffffffffu, incl, off);
            if (lane >= off) incl += t;
        }
        if (lane == 31) swarp[w] = incl;
        __syncthreads();
        if (w == 0) {
            int x = swarp[lane];
#pragma unroll
            for (int off = 1; off < 32; off <<= 1) {
                int t = __shfl_up_sync(0xffffffffu, x, off);
                if (lane >= off) x += t;
            }
            swarp[lane] = x;
        }
        __syncthreads();
        int offset = (w > 0) ? swarp[w - 1] : 0;
        int total = swarp[31];
        incl += offset;
        if (i < NN) {
            g_rowptr[m * (NN + 1) + i + 1] = carry + incl;
            g_cursor[m * NN + i] = carry + incl - v;
        }
        carry += total;
        __syncthreads();
    }
}

// ---------------- CSR: scatter packed payload ----------------
__global__ void k_scatter(const int* __restrict__ ei_all) {
    int e = blockIdx.x * 256 + threadIdx.x;
    if (e >= EE) return;
    int m = blockIdx.y;
    int s = ei_all[m * 2 * EE + e];
    int d = ei_all[m * 2 * EE + EE + e];
    int pos = atomicAdd(&g_cursor[m * NN + d], 1);
    g_sl[(size_t)m * EE + pos] = make_int2(s, __float_as_int(g_lea[(size_t)m * EE + e]));
}

// ---------------- finalize BN affine + per-head edge scalar (de-aliased) -------
template<int H, int C>
__global__ void k_bnfin(const float* __restrict__ lew, const float* __restrict__ aew,
                        const float* __restrict__ gamma, const float* __restrict__ beta,
                        float* __restrict__ edot_out, float* __restrict__ aff_out) {
    int w = threadIdx.x >> 5, lane = threadIdx.x & 31;   // MM*H warps
    int m = w / H, h = w % H;
    float s = 0.f;
    for (int c = lane; c < C; c += 32)
        s += lew[(m * H + h) * C + c] * aew[(m * H + h) * C + c];
#pragma unroll
    for (int o = 16; o; o >>= 1) s += __shfl_down_sync(0xffffffffu, s, o);
    if (lane == 0) edot_out[m * H + h] = s;
    if (threadIdx.x < MM) {
        int mm = threadIdx.x;
        float mu   = g_stats[mm * 2 + 0] * (1.f / EE);
        float var  = g_stats[mm * 2 + 1] * (1.f / EE) - mu * mu;
        float sc   = gamma[mm] * rsqrtf(var + 1e-5f);
        aff_out[mm * 2 + 0] = sc;
        aff_out[mm * 2 + 1] = beta[mm] - mu * sc;
    }
}

// ---------------- SGEMM + fused attention-dot epilogue; fp16 h store -----------
template<int K, int NC, int CT, int H>
__global__ void k_sgemm(const float* __restrict__ X, const float* __restrict__ Wall,
                        const float* __restrict__ asw, const float* __restrict__ adw) {
    constexpr int CP = CT / 16;
    constexpr int RW = 64 / CP;
    extern __shared__ float sm[];
    float* Xs = sm;                  // [64][68]
    float* Ws = sm + 64 * 68;        // [64][CT]
    int m = blockIdx.z;
    const float* W = Wall + (size_t)m * K * NC;
    __half* Hd = g_h + (size_t)m * NN * NC;
    int nb = blockIdx.y * 64, cb = blockIdx.x * CT;
    int tid = threadIdx.x, tx = tid & 15, ty = tid >> 4;
    float acc[4][CP];
#pragma unroll
    for (int i = 0; i < 4; i++)
#pragma unroll
        for (int j = 0; j < CP; j++) acc[i][j] = 0.f;

    for (int kt = 0; kt < K; kt += 64) {
#pragma unroll
        for (int i = 0; i < 4; i++) {
            int v = tid + i * 256;
            int row = v >> 4, kq = (v & 15) << 2;
            int gr = nb + row;
            float4 xv = make_float4(0.f, 0.f, 0.f, 0.f);
            if (gr < NN) xv = *(const float4*)(X + (size_t)gr * K + kt + kq);
            *(float4*)&Xs[row * 68 + kq] = xv;
        }
#pragma unroll
        for (int i = 0; i < CP; i++) {
            int v = tid + i * 256;
            int krow = v / (CT / 4), cq = (v % (CT / 4)) * 4;
            *(float4*)&Ws[krow * CT + cq] = *(const float4*)(W + (size_t)(kt + krow) * NC + cb + cq);
        }
        __syncthreads();
#pragma unroll 8
        for (int k = 0; k < 64; k++) {
            float a[4];
#pragma unroll
            for (int i = 0; i < 4; i++) a[i] = Xs[(ty * 4 + i) * 68 + k];
            float b[CP];
#pragma unroll
            for (int jj = 0; jj < CP / 4; jj++) {
                float4 bv = *(float4*)&Ws[k * CT + tx * CP + 4 * jj];
                b[4 * jj + 0] = bv.x; b[4 * jj + 1] = bv.y;
                b[4 * jj + 2] = bv.z; b[4 * jj + 3] = bv.w;
            }
#pragma unroll
            for (int i = 0; i < 4; i++)
#pragma unroll
                for (int j = 0; j < CP; j++) acc[i][j] += a[i] * b[j];
        }
        __syncthreads();
    }
    // fp16 store of h
#pragma unroll
    for (int i = 0; i < 4; i++) {
        int gr = nb + ty * 4 + i;
        if (gr < NN) {
            if (CP == 8) {
                uint4 pk;
                pk.x = pack2(acc[i][0], acc[i][1]);
                pk.y = pack2(acc[i][2], acc[i][3]);
                pk.z = pack2(acc[i][4], acc[i][5]);
                pk.w = pack2(acc[i][6], acc[i][7]);
                *(uint4*)(Hd + (size_t)gr * NC + cb + tx * CP) = pk;
            } else {
                uint2 pk;
                pk.x = pack2(acc[i][0], acc[i][1]);
                pk.y = pack2(acc[i][2], acc[i][3]);
                *(uint2*)(Hd + (size_t)gr * NC + cb + tx * CP) = pk;
            }
        }
    }
    // fused attention dots (fp32, pre-quantization)
    int colbase = cb + tx * CP;
    int head = colbase / 64;
#pragma unroll
    for (int i = 0; i < 4; i++) {
        float ps = 0.f, pd = 0.f;
#pragma unroll
        for (int j = 0; j < CP; j++) {
            ps += acc[i][j] * asw[m * H * 64 + colbase + j];
            pd += acc[i][j] * adw[m * H * 64 + colbase + j];
        }
#pragma unroll
        for (int off = RW / 2; off; off >>= 1) {
            ps += __shfl_down_sync(0xffffffffu, ps, off, RW);
            pd += __shfl_down_sync(0xffffffffu, pd, off, RW);
        }
        int gr = nb + ty * 4 + i;
        if ((tx & (RW - 1)) == 0 && gr < NN) {
            g_asrc[(size_t)(m * NN + gr) * H + head] = ps;
            g_adst[(size_t)(m * NN + gr) * H + head] = pd;
        }
    }
}

// ---------------- GAT layer 1 (H=4): one warp per node, fp16 gathers ----------
// lane l: head h = l>>3, channels 8l..8l+7 (one uint4 = 8 halves per edge).
// per-head unnormalized accumulate; normalize per head; head-sum via shfl 8,16.
__global__ void k_gat4(const float* __restrict__ bias) {
    __shared__ float s_w[8][64 * 4];
    __shared__ int   s_soff[8][64];
    int w = threadIdx.x >> 5, l = threadIdx.x & 31;
    int m = blockIdx.y;
    int n = blockIdx.x * 8 + w;                 // grid.x = NN/8 exact
    int base = g_rowptr[m * (NN + 1) + n];
    int deg  = g_rowptr[m * (NN + 1) + n + 1] - base;
    float sc = g_aff1[m * 2 + 0], sh = g_aff1[m * 2 + 1];
    float4 edot = *(const float4*)&g_edot1[m * 4];
    float4 adst = *(const float4*)&g_adst[(size_t)(m * NN + n) * 4];
    const int2* slp = g_sl + (size_t)m * EE + base;
    const uint4* hb = (const uint4*)(g_h + (size_t)m * NN * 256);   // 32 uint4/node
    int h = l >> 3;
    float acc[8] = {};
    float den = 0.f;

    for (int cs = 0; cs < deg; cs += 64) {
        int cn = min(64, deg - cs);
        for (int j = l; j < cn; j += 32) {
            int2 sl = slp[cs + j];
            float ea = __int_as_float(sl.y) * sc + sh;
            float4 as = *(const float4*)&g_asrc[(size_t)(m * NN + sl.x) * 4];
            s_soff[w][j] = sl.x * 32;
            float4 wv;
            wv.x = lrelu_exp(as.x + adst.x + ea * edot.x);
            wv.y = lrelu_exp(as.y + adst.y + ea * edot.y);
            wv.z = lrelu_exp(as.z + adst.z + ea * edot.z);
            wv.w = lrelu_exp(as.w + adst.w + ea * edot.w);
            *(float4*)&s_w[w][j * 4] = wv;
        }
        __syncwarp();
#pragma unroll 2
        for (int j = 0; j < cn; j++) {
            float wt = s_w[w][j * 4 + h];
            uint4 hv = hb[s_soff[w][j] + l];
            float2 f;
            f = up2(hv.x); acc[0] += wt * f.x; acc[1] += wt * f.y;
            f = up2(hv.y); acc[2] += wt * f.x; acc[3] += wt * f.y;
            f = up2(hv.z); acc[4] += wt * f.x; acc[5] += wt * f.y;
            f = up2(hv.w); acc[6] += wt * f.x; acc[7] += wt * f.y;
            den += wt;
        }
        __syncwarp();
    }

    // per-head normalize, then sum heads via shfl (lane l += lanes l+8, l+16, l+24)
    float inv = 1.f / (den + 1e-16f);
#pragma unroll
    for (int k = 0; k < 8; k++) {
        float v = acc[k] * inv;
        v += __shfl_down_sync(0xffffffffu, v, 8);
        v += __shfl_down_sync(0xffffffffu, v, 16);
        acc[k] = v;
    }
    if (l < 8) {
        const float* bp = bias + m * 64 + 8 * l;
        float4 r0, r1;
        r0.x = elu1(acc[0] * 0.25f + bp[0]); r0.y = elu1(acc[1] * 0.25f + bp[1]);
        r0.z = elu1(acc[2] * 0.25f + bp[2]); r0.w = elu1(acc[3] * 0.25f + bp[3]);
        r1.x = elu1(acc[4] * 0.25f + bp[4]); r1.y = elu1(acc[5] * 0.25f + bp[5]);
        r1.z = elu1(acc[6] * 0.25f + bp[6]); r1.w = elu1(acc[7] * 0.25f + bp[7]);
        float* zp = &g_zstack[((size_t)n * MM + m) * 64 + 8 * l];
        *(float4*)zp = r0;
        *(float4*)(zp + 4) = r1;
    }
}

// ---------------- GAT layer 2 (H=1): 8 lanes/node, fp16, no smem/syncs --------
__global__ void k_gat1(const float* __restrict__ bias) {
    int tid = threadIdx.x;
    int g = tid >> 3, l8 = tid & 7;
    int m = blockIdx.y;
    int n = blockIdx.x * 32 + g;                // grid.x = NN/32 exact
    int base = g_rowptr[m * (NN + 1) + n];
    int deg  = g_rowptr[m * (NN + 1) + n + 1] - base;
    float sc = g_aff2[m * 2 + 0], sh = g_aff2[m * 2 + 1];
    float edot = g_edot2[m];
    float adst = g_adst[m * NN + n];
    const int2* slp = g_sl + (size_t)m * EE + base;
    const uint4* hb = (const uint4*)(g_h + (size_t)m * NN * 64);    // 8 uint4/node
    const float* asp = g_asrc + (size_t)m * NN;
    float acc[8] = {};
    float den = 0.f;

    for (int j = 0; j < deg; j++) {
        int2 sl = slp[j];
        float ea = __int_as_float(sl.y) * sc + sh;
        float wt = lrelu_exp(asp[sl.x] + adst + ea * edot);
        uint4 hv = hb[sl.x * 8 + l8];
        float2 f;
        f = up2(hv.x); acc[0] += wt * f.x; acc[1] += wt * f.y;
        f = up2(hv.y); acc[2] += wt * f.x; acc[3] += wt * f.y;
        f = up2(hv.z); acc[4] += wt * f.x; acc[5] += wt * f.y;
        f = up2(hv.w); acc[6] += wt * f.x; acc[7] += wt * f.y;
        den += wt;
    }
    float inv = 1.f / (den + 1e-16f);
    const float* bp = bias + m * 64 + 8 * l8;
    float4 r0, r1;
    r0.x = elu1(acc[0] * inv + bp[0]); r0.y = elu1(acc[1] * inv + bp[1]);
    r0.z = elu1(acc[2] * inv + bp[2]); r0.w = elu1(acc[3] * inv + bp[3]);
    r1.x = elu1(acc[4] * inv + bp[4]); r1.y = elu1(acc[5] * inv + bp[5]);
    r1.z = elu1(acc[6] * inv + bp[6]); r1.w = elu1(acc[7] * inv + bp[7]);
    float* zp = &g_zstack[((size_t)n * MM + m) * 64 + 8 * l8];
    *(float4*)zp = r0;
    *(float4*)(zp + 4) = r1;
}

// ---------------- semantic attention over M (4 nodes per block) ----------------
__global__ void k_semantic(const float* __restrict__ semw, const float* __restrict__ semb,
                           const float* __restrict__ semv,
                           float* __restrict__ out, float* beta_out) {
    __shared__ float zsh[4][MM][CC];
    __shared__ float wred[4][2];
    __shared__ float ssc[4][MM];
    int g = threadIdx.x >> 6, c = threadIdx.x & 63;
    int n = blockIdx.x * 4 + g;
    bool ok = n < NN;
#pragma unroll
    for (int m = 0; m < MM; m++)
        zsh[g][m][c] = ok ? g_zstack[((size_t)n * MM + m) * CC + c] : 0.f;
    __syncthreads();
#pragma unroll
    for (int m = 0; m < MM; m++) {
        float acc = semb[c];
#pragma unroll 16
        for (int k = 0; k < CC; k++) acc += zsh[g][m][k] * semw[k * CC + c];
        float v = tanhf(acc) * semv[c];
#pragma unroll
        for (int o = 16; o; o >>= 1) v += __shfl_down_sync(0xffffffffu, v, o);
        if ((c & 31) == 0) wred[g][c >> 5] = v;
        __syncthreads();
        if (c == 0) ssc[g][m] = wred[g][0] + wred[g][1];
        __syncthreads();
    }
    if (c == 0) {
        float mx = fmaxf(ssc[g][0], fmaxf(ssc[g][1], ssc[g][2]));
        float e0 = expf(ssc[g][0] - mx), e1 = expf(ssc[g][1] - mx), e2 = expf(ssc[g][2] - mx);
        float inv = 1.f / (e0 + e1 + e2);
        ssc[g][0] = e0 * inv; ssc[g][1] = e1 * inv; ssc[g][2] = e2 * inv;
    }
    __syncthreads();
    if (ok) {
        out[(size_t)n * CC + c] = zsh[g][0][c] * ssc[g][0] + zsh[g][1][c] * ssc[g][1] + zsh[g][2][c] * ssc[g][2];
        if (beta_out != nullptr && c < MM) beta_out[n * MM + c] = ssc[g][c];
    }
}

// ---------------- tiled fused decoder ----------------
__global__ void k_decoder(const float* __restrict__ z,
                          const float* __restrict__ w1, const float* __restrict__ b1,
                          const float* __restrict__ w2, const float* __restrict__ b2,
                          float* __restrict__ xhat) {
    extern __shared__ float sm[];
    float* Ts  = sm;               // [64][65]
    float* Zs  = sm + 4160;        // [64][65]
    float* W1s = sm + 8320;        // [64][64]
    float* W2s = sm + 4160;        // [64][128], overlays phase-1 space
    int nb = blockIdx.x * 64;
    int tid = threadIdx.x;
    int tx = tid & 15, ty = tid >> 4;
#pragma unroll
    for (int i = 0; i < 4; i++) {
        int v = tid + i * 256;
        int row = v >> 4, kq = (v & 15) << 2;
        int gr = nb + row;
        float4 zv = make_float4(0.f, 0.f, 0.f, 0.f);
        if (gr < NN) zv = *(const float4*)(z + (size_t)gr * CC + kq);
        Zs[row * 65 + kq + 0] = zv.x; Zs[row * 65 + kq + 1] = zv.y;
        Zs[row * 65 + kq + 2] = zv.z; Zs[row * 65 + kq + 3] = zv.w;
        *(float4*)&W1s[row * 64 + kq] = *(const float4*)(w1 + row * CC + kq);
    }
    __syncthreads();
    {
        float acc[4][4];
#pragma unroll
        for (int j = 0; j < 4; j++) {
            float bv = b1[tx * 4 + j];
#pragma unroll
            for (int i = 0; i < 4; i++) acc[i][j] = bv;
        }
#pragma unroll 16
        for (int k = 0; k < 64; k++) {
            float a0 = Zs[(ty * 4 + 0) * 65 + k];
            float a1 = Zs[(ty * 4 + 1) * 65 + k];
            float a2 = Zs[(ty * 4 + 2) * 65 + k];
            float a3 = Zs[(ty * 4 + 3) * 65 + k];
            float4 b = *(float4*)&W1s[k * 64 + tx * 4];
            acc[0][0] += a0 * b.x; acc[0][1] += a0 * b.y; acc[0][2] += a0 * b.z; acc[0][3] += a0 * b.w;
            acc[1][0] += a1 * b.x; acc[1][1] += a1 * b.y; acc[1][2] += a1 * b.z; acc[1][3] += a1 * b.w;
            acc[2][0] += a2 * b.x; acc[2][1] += a2 * b.y; acc[2][2] += a2 * b.z; acc[2][3] += a2 * b.w;
            acc[3][0] += a3 * b.x; acc[3][1] += a3 * b.y; acc[3][2] += a3 * b.z; acc[3][3] += a3 * b.w;
        }
#pragma unroll
        for (int i = 0; i < 4; i++)
#pragma unroll
            for (int j = 0; j < 4; j++)
                Ts[(ty * 4 + i) * 65 + tx * 4 + j] = elu1(acc[i][j]);
    }
    __syncthreads();
#pragma unroll
    for (int i = 0; i < 8; i++) {
        int v = tid + i * 256;
        int k = v >> 5, cq = (v & 31) << 2;
        *(float4*)&W2s[k * 128 + cq] = *(const float4*)(w2 + k * FIN + cq);
    }
    __syncthreads();
    {
        float acc[4][8];
#pragma unroll
        for (int j = 0; j < 4; j++) {
            float bva = b2[tx * 4 + j], bvb = b2[64 + tx * 4 + j];
#pragma unroll
            for (int i = 0; i < 4; i++) { acc[i][j] = bva; acc[i][j + 4] = bvb; }
        }
#pragma unroll 8
        for (int k = 0; k < 64; k++) {
            float a0 = Ts[(ty * 4 + 0) * 65 + k];
            float a1 = Ts[(ty * 4 + 1) * 65 + k];
            float a2 = Ts[(ty * 4 + 2) * 65 + k];
            float a3 = Ts[(ty * 4 + 3) * 65 + k];
            float4 ba = *(float4*)&W2s[k * 128 + tx * 4];
            float4 bb = *(float4*)&W2s[k * 128 + 64 + tx * 4];
            acc[0][0] += a0 * ba.x; acc[0][1] += a0 * ba.y; acc[0][2] += a0 * ba.z; acc[0][3] += a0 * ba.w;
            acc[1][0] += a1 * ba.x; acc[1][1] += a1 * ba.y; acc[1][2] += a1 * ba.z; acc[1][3] += a1 * ba.w;
            acc[2][0] += a2 * ba.x; acc[2][1] += a2 * ba.y; acc[2][2] += a2 * ba.z; acc[2][3] += a2 * ba.w;
            acc[3][0] += a3 * ba.x; acc[3][1] += a3 * ba.y; acc[3][2] += a3 * ba.z; acc[3][3] += a3 * ba.w;
            acc[0][4] += a0 * bb.x; acc[0][5] += a0 * bb.y; acc[0][6] += a0 * bb.z; acc[0][7] += a0 * bb.w;
            acc[1][4] += a1 * bb.x; acc[1][5] += a1 * bb.y; acc[1][6] += a1 * bb.z; acc[1][7] += a1 * bb.w;
            acc[2][4] += a2 * bb.x; acc[2][5] += a2 * bb.y; acc[2][6] += a2 * bb.z; acc[2][7] += a2 * bb.w;
            acc[3][4] += a3 * bb.x; acc[3][5] += a3 * bb.y; acc[3][6] += a3 * bb.z; acc[3][7] += a3 * bb.w;
        }
#pragma unroll
        for (int i = 0; i < 4; i++) {
            int gr = nb + ty * 4 + i;
            if (gr < NN) {
                *(float4*)(xhat + (size_t)gr * FIN + tx * 4) =
                    make_float4(acc[i][0], acc[i][1], acc[i][2], acc[i][3]);
                *(float4*)(xhat + (size_t)gr * FIN + 64 + tx * 4) =
                    make_float4(acc[i][4], acc[i][5], acc[i][6], acc[i][7]);
            }
        }
    }
}

// ---------------- host (stream-forked CSR build) ----------------
extern "C" void kernel_launch(void* const* d_in, const int* in_sizes, int n_in,
                              void* d_out, int out_size) {
    const float* x      = (const float*)d_in[0];
    const int*   ei     = (const int*)  d_in[1];   // [M,2,E]
    const float* eattr  = (const float*)d_in[2];   // [M,E,1]
    const float* lin1w  = (const float*)d_in[3];
    const float* a1s    = (const float*)d_in[4];
    const float* a1d    = (const float*)d_in[5];
    const float* l1e    = (const float*)d_in[6];
    const float* a1e    = (const float*)d_in[7];
    const float* b1     = (const float*)d_in[8];
    const float* bn1g   = (const float*)d_in[9];
    const float* bn1b   = (const float*)d_in[10];
    const float* sem1w  = (const float*)d_in[11];
    const float* sem1b  = (const float*)d_in[12];
    const float* sem1v  = (const float*)d_in[13];
    const float* lin2w  = (const float*)d_in[14];
    const float* a2s    = (const float*)d_in[15];
    const float* a2d    = (const float*)d_in[16];
    const float* l2e    = (const float*)d_in[17];
    const float* a2e    = (const float*)d_in[18];
    const float* b2     = (const float*)d_in[19];
    const float* bn2g   = (const float*)d_in[20];
    const float* bn2b   = (const float*)d_in[21];
    const float* sem2w  = (const float*)d_in[22];
    const float* sem2b  = (const float*)d_in[23];
    const float* sem2v  = (const float*)d_in[24];
    const float* dec1w  = (const float*)d_in[25];
    const float* dec1b  = (const float*)d_in[26];
    const float* dec2w  = (const float*)d_in[27];
    const float* dec2b  = (const float*)d_in[28];

    float* z_out    = (float*)d_out;             // [N, C2]
    float* xhat     = z_out + NN * CC;           // [N, IN]
    float* beta_out = xhat + NN * FIN;           // [N, M]

    float* houtp = nullptr;
    cudaGetSymbolAddress((void**)&houtp, g_hout);
    float *edot1p = nullptr, *edot2p = nullptr, *aff1p = nullptr, *aff2p = nullptr;
    cudaGetSymbolAddress((void**)&edot1p, g_edot1);
    cudaGetSymbolAddress((void**)&edot2p, g_edot2);
    cudaGetSymbolAddress((void**)&aff1p, g_aff1);
    cudaGetSymbolAddress((void**)&aff2p, g_aff2);

    const int EB = (EE + 255) / 256;
    const int NB64 = (NN + 63) / 64;

    int smem1 = (64 * 68 + 64 * 128) * 4;   // 50176
    int smem2 = (64 * 68 + 64 * 64) * 4;    // 33792

    static cudaStream_t s2;
    static cudaEvent_t evA, evB;
    static bool init_done = false;
    if (!init_done) {
        cudaFuncSetAttribute(k_sgemm<FIN, HH * CC, 128, HH>, cudaFuncAttributeMaxDynamicSharedMemorySize, smem1);
        cudaFuncSetAttribute(k_sgemm<CC, CC, 64, 1>, cudaFuncAttributeMaxDynamicSharedMemorySize, smem2);
        cudaFuncSetAttribute(k_decoder, cudaFuncAttributeMaxDynamicSharedMemorySize, 12416 * 4);
        cudaStreamCreateWithFlags(&s2, cudaStreamNonBlocking);
        cudaEventCreateWithFlags(&evA, cudaEventDisableTiming);
        cudaEventCreateWithFlags(&evB, cudaEventDisableTiming);
        init_done = true;
    }

    // ---- fork: CSR build + BN on s2, concurrent with sgemm1 on origin stream ----
    cudaEventRecord(evA, 0);
    cudaStreamWaitEvent(s2, evA, 0);
    k_zero1<<<(MM * NN + 255) / 256, 256, 0, s2>>>();
    k_build<<<dim3(EB, MM), 256, 0, s2>>>(ei, eattr);
    k_scan<<<MM, 1024, 0, s2>>>();
    k_scatter<<<dim3(EB, MM), 256, 0, s2>>>(ei);
    k_bnfin<HH, CC><<<1, MM * HH * 32, 0, s2>>>(l1e, a1e, bn1g, bn1b, edot1p, aff1p);
    k_bnfin<1, CC><<<1, MM * 32, 0, s2>>>(l2e, a2e, bn2g, bn2b, edot2p, aff2p);
    cudaEventRecord(evB, s2);

    k_sgemm<FIN, HH * CC, 128, HH><<<dim3(2, NB64, MM), 256, smem1>>>(x, lin1w, a1s, a1d);
    cudaStreamWaitEvent(0, evB, 0);

    // ---- HAN layer 1 (heads = 4) ----
    k_gat4<<<dim3(NN / 8, MM), 256>>>(b1);
    k_semantic<<<(NN + 3) / 4, 256>>>(sem1w, sem1b, sem1v, houtp, nullptr);

    // ---- HAN layer 2 (heads = 1) ----
    k_sgemm<CC, CC, 64, 1><<<dim3(1, NB64, MM), 256, smem2>>>(houtp, lin2w, a2s, a2d);
    k_gat1<<<dim3(NN / 32, MM), 256>>>(b2);
    k_semantic<<<(NN + 3) / 4, 256>>>(sem2w, sem2b, sem2v, z_out, beta_out);

    // ---- decoder ----
    k_decoder<<<NB64, 256, 12416 * 4>>>(z_out, dec1w, dec1b, dec2w, dec2b, xhat);
}

// round 14
// speedup vs baseline: 3.1621x; 1.1018x over previous
#include <cuda_runtime.h>
#include <cuda_fp16.h>
#include <math.h>
#include <float.h>

#define NN 20000
#define EE 320000
#define MM 3
#define FIN 128
#define HH 4
#define CC 64
#define NEG_SLOPE 0.2f

// ---------------- scratch (device globals) ----------------
__device__ __align__(16) __half g_h[MM * NN * HH * CC];    // projected features (fp16)
__device__ __align__(16) float g_asrc[MM * NN * HH];
__device__ __align__(16) float g_adst[MM * NN * HH];
__device__ __align__(16) float g_zstack[NN * MM * CC];
__device__ __align__(16) float g_hout[NN * CC];
__device__ float g_stats[MM * 2];                           // per m: sum, sumsq (raw only)
__device__ __align__(16) float g_edot1[MM * HH];            // layer-1 per-head edge scalars
__device__ float g_edot2[MM];                               // layer-2 edge scalars
__device__ float g_aff1[MM * 2];                            // layer-1 BN scale/shift
__device__ float g_aff2[MM * 2];                            // layer-2 BN scale/shift
// CSR: payload packed {src, log1p(attr)} in CSR order
__device__ int   g_deg[MM * NN];
__device__ int   g_rowptr[MM * (NN + 1)];
__device__ int   g_cursor[MM * NN];
__device__ float g_lea[MM * EE];                            // log1p(attr), edge order
__device__ __align__(8) int2 g_sl[MM * EE];                 // {src, bitcast lea}, CSR order

// ---------------- helpers ----------------
__device__ __forceinline__ float elu1(float x) { return x > 0.f ? x : expm1f(x); }
__device__ __forceinline__ float lrelu_exp(float a) {
    a = a > 0.f ? a : NEG_SLOPE * a;
    return expf(a);
}
__device__ __forceinline__ unsigned pack2(float a, float b) {
    __half2 h = __float22half2_rn(make_float2(a, b));
    return *(unsigned*)&h;
}
__device__ __forceinline__ float2 up2(unsigned u) {
    return __half22float2(*(__half2*)&u);
}

// ---------------- zero init ----------------
__global__ void k_zero1() {
    int i = blockIdx.x * blockDim.x + threadIdx.x;
    if (i < MM * NN) g_deg[i] = 0;
    if (i < MM * 2) g_stats[i] = 0.f;
}

// ---------------- fused: degree histogram + log1p + BN stats ----------------
__global__ void k_build(const int* __restrict__ ei_all, const float* __restrict__ attr) {
    int m = blockIdx.y;
    int e = blockIdx.x * 256 + threadIdx.x;
    float v = 0.f, v2 = 0.f;
    if (e < EE) {
        atomicAdd(&g_deg[m * NN + ei_all[m * 2 * EE + EE + e]], 1);
        float t = log1pf(attr[m * EE + e]);
        g_lea[(size_t)m * EE + e] = t;
        v = t; v2 = t * t;
    }
#pragma unroll
    for (int o = 16; o; o >>= 1) {
        v  += __shfl_down_sync(0xffffffffu, v,  o);
        v2 += __shfl_down_sync(0xffffffffu, v2, o);
    }
    __shared__ float s1[8], s2[8];
    int lane = threadIdx.x & 31, w = threadIdx.x >> 5;
    if (lane == 0) { s1[w] = v; s2[w] = v2; }
    __syncthreads();
    if (threadIdx.x == 0) {
        float a = 0.f, b = 0.f;
        for (int j = 0; j < 8; j++) { a += s1[j]; b += s2[j]; }
        atomicAdd(&g_stats[m * 2 + 0], a);
        atomicAdd(&g_stats[m * 2 + 1], b);
    }
}

// ---------------- CSR: exclusive scan (one block per metapath) ----------------
__global__ void k_scan() {
    int m = blockIdx.x;
    __shared__ int swarp[32];
    int tid = threadIdx.x, lane = tid & 31, w = tid >> 5;
    int carry = 0;
    if (tid == 0) g_rowptr[m * (NN + 1)] = 0;
    for (int c0 = 0; c0 < NN; c0 += 1024) {
        int i = c0 + tid;
        int v = (i < NN) ? g_deg[m * NN + i] : 0;
        int incl = v;
#pragma unroll
        for (int off = 1; off < 32; off <<= 1) {
            int t = __shfl_up_sync(0xffffffffu, incl, off);
            if (lane >= off) incl += t;
        }
        if (lane == 31) swarp[w] = incl;
        __syncthreads();
        if (w == 0) {
            int x = swarp[lane];
#pragma unroll
            for (int off = 1; off < 32; off <<= 1) {
                int t = __shfl_up_sync(0xffffffffu, x, off);
                if (lane >= off) x += t;
            }
            swarp[lane] = x;
        }
        __syncthreads();
        int offset = (w > 0) ? swarp[w - 1] : 0;
        int total = swarp[31];
        incl += offset;
        if (i < NN) {
            g_rowptr[m * (NN + 1) + i + 1] = carry + incl;
            g_cursor[m * NN + i] = carry + incl - v;
        }
        carry += total;
        __syncthreads();
    }
}

// ---------------- CSR: scatter packed payload ----------------
__global__ void k_scatter(const int* __restrict__ ei_all) {
    int e = blockIdx.x * 256 + threadIdx.x;
    if (e >= EE) return;
    int m = blockIdx.y;
    int s = ei_all[m * 2 * EE + e];
    int d = ei_all[m * 2 * EE + EE + e];
    int pos = atomicAdd(&g_cursor[m * NN + d], 1);
    g_sl[(size_t)m * EE + pos] = make_int2(s, __float_as_int(g_lea[(size_t)m * EE + e]));
}

// ---------------- finalize BN affine + per-head edge scalar (de-aliased) -------
template<int H, int C>
__global__ void k_bnfin(const float* __restrict__ lew, const float* __restrict__ aew,
                        const float* __restrict__ gamma, const float* __restrict__ beta,
                        float* __restrict__ edot_out, float* __restrict__ aff_out) {
    int w = threadIdx.x >> 5, lane = threadIdx.x & 31;   // MM*H warps
    int m = w / H, h = w % H;
    float s = 0.f;
    for (int c = lane; c < C; c += 32)
        s += lew[(m * H + h) * C + c] * aew[(m * H + h) * C + c];
#pragma unroll
    for (int o = 16; o; o >>= 1) s += __shfl_down_sync(0xffffffffu, s, o);
    if (lane == 0) edot_out[m * H + h] = s;
    if (threadIdx.x < MM) {
        int mm = threadIdx.x;
        float mu   = g_stats[mm * 2 + 0] * (1.f / EE);
        float var  = g_stats[mm * 2 + 1] * (1.f / EE) - mu * mu;
        float sc   = gamma[mm] * rsqrtf(var + 1e-5f);
        aff_out[mm * 2 + 0] = sc;
        aff_out[mm * 2 + 1] = beta[mm] - mu * sc;
    }
}

// ---------------- layer-1 SGEMM: 128x128 tile, 8x8 microtile, fp16 h store -----
// thread = 8 rows x 8 cols; per k: 8 scalar LDS (a) + 2 LDS.128 (b) per 64 FMA.
template<int K, int NC, int H>
__global__ void __launch_bounds__(256, 2) k_sgemm1(
        const float* __restrict__ X, const float* __restrict__ Wall,
        const float* __restrict__ asw, const float* __restrict__ adw) {
    __shared__ float Xs[128][33];
    __shared__ float Ws[32][128];
    int m = blockIdx.z;
    const float* W = Wall + (size_t)m * K * NC;
    __half* Hd = g_h + (size_t)m * NN * NC;
    int nb = blockIdx.y * 128, cb = blockIdx.x * 128;
    int tid = threadIdx.x, tx = tid & 15, ty = tid >> 4;
    float acc[8][8];
#pragma unroll
    for (int i = 0; i < 8; i++)
#pragma unroll
        for (int j = 0; j < 8; j++) acc[i][j] = 0.f;

    for (int kt = 0; kt < K; kt += 32) {
        // X tile: 128 rows x 32 k
#pragma unroll
        for (int i = 0; i < 4; i++) {
            int v = tid + i * 256;
            int row = v >> 3, kq = (v & 7) << 2;
            int gr = nb + row;
            float4 xv = make_float4(0.f, 0.f, 0.f, 0.f);
            if (gr < NN) xv = *(const float4*)(X + (size_t)gr * K + kt + kq);
            Xs[row][kq + 0] = xv.x; Xs[row][kq + 1] = xv.y;
            Xs[row][kq + 2] = xv.z; Xs[row][kq + 3] = xv.w;
        }
        // W tile: 32 k x 128 cols
#pragma unroll
        for (int i = 0; i < 4; i++) {
            int v = tid + i * 256;
            int kr = v >> 5, cq = (v & 31) << 2;
            *(float4*)&Ws[kr][cq] = *(const float4*)(W + (size_t)(kt + kr) * NC + cb + cq);
        }
        __syncthreads();
#pragma unroll 4
        for (int k = 0; k < 32; k++) {
            float a[8];
#pragma unroll
            for (int i = 0; i < 8; i++) a[i] = Xs[ty * 8 + i][k];
            float b[8];
            float4 b0 = *(float4*)&Ws[k][tx * 8];
            float4 b1 = *(float4*)&Ws[k][tx * 8 + 4];
            b[0] = b0.x; b[1] = b0.y; b[2] = b0.z; b[3] = b0.w;
            b[4] = b1.x; b[5] = b1.y; b[6] = b1.z; b[7] = b1.w;
#pragma unroll
            for (int i = 0; i < 8; i++)
#pragma unroll
                for (int j = 0; j < 8; j++) acc[i][j] += a[i] * b[j];
        }
        __syncthreads();
    }
    // fp16 store of h (8 rows x 8 cols per thread, one uint4 per row)
#pragma unroll
    for (int i = 0; i < 8; i++) {
        int gr = nb + ty * 8 + i;
        if (gr < NN) {
            uint4 pk;
            pk.x = pack2(acc[i][0], acc[i][1]);
            pk.y = pack2(acc[i][2], acc[i][3]);
            pk.z = pack2(acc[i][4], acc[i][5]);
            pk.w = pack2(acc[i][6], acc[i][7]);
            *(uint4*)(Hd + (size_t)gr * NC + cb + tx * 8) = pk;
        }
    }
    // fused attention dots (fp32, pre-quantization); 8 cols per thread lie in ONE head
    int colbase = cb + tx * 8;
    int head = colbase >> 6;            // 64 cols per head
#pragma unroll
    for (int i = 0; i < 8; i++) {
        float ps = 0.f, pd = 0.f;
#pragma unroll
        for (int j = 0; j < 8; j++) {
            ps += acc[i][j] * asw[m * H * 64 + colbase + j];
            pd += acc[i][j] * adw[m * H * 64 + colbase + j];
        }
        // reduce over the 8 threads (tx group of 8) covering this head
        ps += __shfl_down_sync(0xffffffffu, ps, 4, 8);
        pd += __shfl_down_sync(0xffffffffu, pd, 4, 8);
        ps += __shfl_down_sync(0xffffffffu, ps, 2, 8);
        pd += __shfl_down_sync(0xffffffffu, pd, 2, 8);
        ps += __shfl_down_sync(0xffffffffu, ps, 1, 8);
        pd += __shfl_down_sync(0xffffffffu, pd, 1, 8);
        int gr = nb + ty * 8 + i;
        if ((tx & 7) == 0 && gr < NN) {
            g_asrc[(size_t)(m * NN + gr) * H + head] = ps;
            g_adst[(size_t)(m * NN + gr) * H + head] = pd;
        }
    }
}

// ---------------- layer-2 SGEMM (64 cols): unchanged structure ----------------
template<int K, int NC, int CT, int H>
__global__ void k_sgemm(const float* __restrict__ X, const float* __restrict__ Wall,
                        const float* __restrict__ asw, const float* __restrict__ adw) {
    constexpr int CP = CT / 16;
    constexpr int RW = 64 / CP;
    extern __shared__ float sm[];
    float* Xs = sm;                  // [64][68]
    float* Ws = sm + 64 * 68;        // [64][CT]
    int m = blockIdx.z;
    const float* W = Wall + (size_t)m * K * NC;
    __half* Hd = g_h + (size_t)m * NN * NC;
    int nb = blockIdx.y * 64, cb = blockIdx.x * CT;
    int tid = threadIdx.x, tx = tid & 15, ty = tid >> 4;
    float acc[4][CP];
#pragma unroll
    for (int i = 0; i < 4; i++)
#pragma unroll
        for (int j = 0; j < CP; j++) acc[i][j] = 0.f;

    for (int kt = 0; kt < K; kt += 64) {
#pragma unroll
        for (int i = 0; i < 4; i++) {
            int v = tid + i * 256;
            int row = v >> 4, kq = (v & 15) << 2;
            int gr = nb + row;
            float4 xv = make_float4(0.f, 0.f, 0.f, 0.f);
            if (gr < NN) xv = *(const float4*)(X + (size_t)gr * K + kt + kq);
            *(float4*)&Xs[row * 68 + kq] = xv;
        }
#pragma unroll
        for (int i = 0; i < CP; i++) {
            int v = tid + i * 256;
            int krow = v / (CT / 4), cq = (v % (CT / 4)) * 4;
            *(float4*)&Ws[krow * CT + cq] = *(const float4*)(W + (size_t)(kt + krow) * NC + cb + cq);
        }
        __syncthreads();
#pragma unroll 8
        for (int k = 0; k < 64; k++) {
            float a[4];
#pragma unroll
            for (int i = 0; i < 4; i++) a[i] = Xs[(ty * 4 + i) * 68 + k];
            float b[CP];
#pragma unroll
            for (int jj = 0; jj < CP / 4; jj++) {
                float4 bv = *(float4*)&Ws[k * CT + tx * CP + 4 * jj];
                b[4 * jj + 0] = bv.x; b[4 * jj + 1] = bv.y;
                b[4 * jj + 2] = bv.z; b[4 * jj + 3] = bv.w;
            }
#pragma unroll
            for (int i = 0; i < 4; i++)
#pragma unroll
                for (int j = 0; j < CP; j++) acc[i][j] += a[i] * b[j];
        }
        __syncthreads();
    }
#pragma unroll
    for (int i = 0; i < 4; i++) {
        int gr = nb + ty * 4 + i;
        if (gr < NN) {
            uint2 pk;
            pk.x = pack2(acc[i][0], acc[i][1]);
            pk.y = pack2(acc[i][2], acc[i][3]);
            *(uint2*)(Hd + (size_t)gr * NC + cb + tx * CP) = pk;
        }
    }
    int colbase = cb + tx * CP;
    int head = colbase / 64;
#pragma unroll
    for (int i = 0; i < 4; i++) {
        float ps = 0.f, pd = 0.f;
#pragma unroll
        for (int j = 0; j < CP; j++) {
            ps += acc[i][j] * asw[m * H * 64 + colbase + j];
            pd += acc[i][j] * adw[m * H * 64 + colbase + j];
        }
#pragma unroll
        for (int off = RW / 2; off; off >>= 1) {
            ps += __shfl_down_sync(0xffffffffu, ps, off, RW);
            pd += __shfl_down_sync(0xffffffffu, pd, off, RW);
        }
        int gr = nb + ty * 4 + i;
        if ((tx & (RW - 1)) == 0 && gr < NN) {
            g_asrc[(size_t)(m * NN + gr) * H + head] = ps;
            g_adst[(size_t)(m * NN + gr) * H + head] = pd;
        }
    }
}

// ---------------- GAT layer 1 (H=4): one warp per node, fp16 gathers ----------
__global__ void k_gat4(const float* __restrict__ bias) {
    __shared__ float s_w[8][64 * 4];
    __shared__ int   s_soff[8][64];
    int w = threadIdx.x >> 5, l = threadIdx.x & 31;
    int m = blockIdx.y;
    int n = blockIdx.x * 8 + w;                 // grid.x = NN/8 exact
    int base = g_rowptr[m * (NN + 1) + n];
    int deg  = g_rowptr[m * (NN + 1) + n + 1] - base;
    float sc = g_aff1[m * 2 + 0], sh = g_aff1[m * 2 + 1];
    float4 edot = *(const float4*)&g_edot1[m * 4];
    float4 adst = *(const float4*)&g_adst[(size_t)(m * NN + n) * 4];
    const int2* slp = g_sl + (size_t)m * EE + base;
    const uint4* hb = (const uint4*)(g_h + (size_t)m * NN * 256);   // 32 uint4/node
    int h = l >> 3;
    float acc[8] = {};
    float den = 0.f;

    for (int cs = 0; cs < deg; cs += 64) {
        int cn = min(64, deg - cs);
        for (int j = l; j < cn; j += 32) {
            int2 sl = slp[cs + j];
            float ea = __int_as_float(sl.y) * sc + sh;
            float4 as = *(const float4*)&g_asrc[(size_t)(m * NN + sl.x) * 4];
            s_soff[w][j] = sl.x * 32;
            float4 wv;
            wv.x = lrelu_exp(as.x + adst.x + ea * edot.x);
            wv.y = lrelu_exp(as.y + adst.y + ea * edot.y);
            wv.z = lrelu_exp(as.z + adst.z + ea * edot.z);
            wv.w = lrelu_exp(as.w + adst.w + ea * edot.w);
            *(float4*)&s_w[w][j * 4] = wv;
        }
        __syncwarp();
#pragma unroll 2
        for (int j = 0; j < cn; j++) {
            float wt = s_w[w][j * 4 + h];
            uint4 hv = hb[s_soff[w][j] + l];
            float2 f;
            f = up2(hv.x); acc[0] += wt * f.x; acc[1] += wt * f.y;
            f = up2(hv.y); acc[2] += wt * f.x; acc[3] += wt * f.y;
            f = up2(hv.z); acc[4] += wt * f.x; acc[5] += wt * f.y;
            f = up2(hv.w); acc[6] += wt * f.x; acc[7] += wt * f.y;
            den += wt;
        }
        __syncwarp();
    }

    float inv = 1.f / (den + 1e-16f);
#pragma unroll
    for (int k = 0; k < 8; k++) {
        float v = acc[k] * inv;
        v += __shfl_down_sync(0xffffffffu, v, 8);
        v += __shfl_down_sync(0xffffffffu, v, 16);
        acc[k] = v;
    }
    if (l < 8) {
        const float* bp = bias + m * 64 + 8 * l;
        float4 r0, r1;
        r0.x = elu1(acc[0] * 0.25f + bp[0]); r0.y = elu1(acc[1] * 0.25f + bp[1]);
        r0.z = elu1(acc[2] * 0.25f + bp[2]); r0.w = elu1(acc[3] * 0.25f + bp[3]);
        r1.x = elu1(acc[4] * 0.25f + bp[4]); r1.y = elu1(acc[5] * 0.25f + bp[5]);
        r1.z = elu1(acc[6] * 0.25f + bp[6]); r1.w = elu1(acc[7] * 0.25f + bp[7]);
        float* zp = &g_zstack[((size_t)n * MM + m) * 64 + 8 * l];
        *(float4*)zp = r0;
        *(float4*)(zp + 4) = r1;
    }
}

// ---------------- GAT layer 2 (H=1): 8 lanes/node, fp16, no smem/syncs --------
__global__ void k_gat1(const float* __restrict__ bias) {
    int tid = threadIdx.x;
    int g = tid >> 3, l8 = tid & 7;
    int m = blockIdx.y;
    int n = blockIdx.x * 32 + g;                // grid.x = NN/32 exact
    int base = g_rowptr[m * (NN + 1) + n];
    int deg  = g_rowptr[m * (NN + 1) + n + 1] - base;
    float sc = g_aff2[m * 2 + 0], sh = g_aff2[m * 2 + 1];
    float edot = g_edot2[m];
    float adst = g_adst[m * NN + n];
    const int2* slp = g_sl + (size_t)m * EE + base;
    const uint4* hb = (const uint4*)(g_h + (size_t)m * NN * 64);    // 8 uint4/node
    const float* asp = g_asrc + (size_t)m * NN;
    float acc[8] = {};
    float den = 0.f;

    for (int j = 0; j < deg; j++) {
        int2 sl = slp[j];
        float ea = __int_as_float(sl.y) * sc + sh;
        float wt = lrelu_exp(asp[sl.x] + adst + ea * edot);
        uint4 hv = hb[sl.x * 8 + l8];
        float2 f;
        f = up2(hv.x); acc[0] += wt * f.x; acc[1] += wt * f.y;
        f = up2(hv.y); acc[2] += wt * f.x; acc[3] += wt * f.y;
        f = up2(hv.z); acc[4] += wt * f.x; acc[5] += wt * f.y;
        f = up2(hv.w); acc[6] += wt * f.x; acc[7] += wt * f.y;
        den += wt;
    }
    float inv = 1.f / (den + 1e-16f);
    const float* bp = bias + m * 64 + 8 * l8;
    float4 r0, r1;
    r0.x = elu1(acc[0] * inv + bp[0]); r0.y = elu1(acc[1] * inv + bp[1]);
    r0.z = elu1(acc[2] * inv + bp[2]); r0.w = elu1(acc[3] * inv + bp[3]);
    r1.x = elu1(acc[4] * inv + bp[4]); r1.y = elu1(acc[5] * inv + bp[5]);
    r1.z = elu1(acc[6] * inv + bp[6]); r1.w = elu1(acc[7] * inv + bp[7]);
    float* zp = &g_zstack[((size_t)n * MM + m) * 64 + 8 * l8];
    *(float4*)zp = r0;
    *(float4*)(zp + 4) = r1;
}

// ---------------- semantic attention over M (4 nodes per block) ----------------
__global__ void k_semantic(const float* __restrict__ semw, const float* __restrict__ semb,
                           const float* __restrict__ semv,
                           float* __restrict__ out, float* beta_out) {
    __shared__ float zsh[4][MM][CC];
    __shared__ float wred[4][2];
    __shared__ float ssc[4][MM];
    int g = threadIdx.x >> 6, c = threadIdx.x & 63;
    int n = blockIdx.x * 4 + g;
    bool ok = n < NN;
#pragma unroll
    for (int m = 0; m < MM; m++)
        zsh[g][m][c] = ok ? g_zstack[((size_t)n * MM + m) * CC + c] : 0.f;
    __syncthreads();
#pragma unroll
    for (int m = 0; m < MM; m++) {
        float acc = semb[c];
#pragma unroll 16
        for (int k = 0; k < CC; k++) acc += zsh[g][m][k] * semw[k * CC + c];
        float v = tanhf(acc) * semv[c];
#pragma unroll
        for (int o = 16; o; o >>= 1) v += __shfl_down_sync(0xffffffffu, v, o);
        if ((c & 31) == 0) wred[g][c >> 5] = v;
        __syncthreads();
        if (c == 0) ssc[g][m] = wred[g][0] + wred[g][1];
        __syncthreads();
    }
    if (c == 0) {
        float mx = fmaxf(ssc[g][0], fmaxf(ssc[g][1], ssc[g][2]));
        float e0 = expf(ssc[g][0] - mx), e1 = expf(ssc[g][1] - mx), e2 = expf(ssc[g][2] - mx);
        float inv = 1.f / (e0 + e1 + e2);
        ssc[g][0] = e0 * inv; ssc[g][1] = e1 * inv; ssc[g][2] = e2 * inv;
    }
    __syncthreads();
    if (ok) {
        out[(size_t)n * CC + c] = zsh[g][0][c] * ssc[g][0] + zsh[g][1][c] * ssc[g][1] + zsh[g][2][c] * ssc[g][2];
        if (beta_out != nullptr && c < MM) beta_out[n * MM + c] = ssc[g][c];
    }
}

// ---------------- tiled fused decoder ----------------
__global__ void k_decoder(const float* __restrict__ z,
                          const float* __restrict__ w1, const float* __restrict__ b1,
                          const float* __restrict__ w2, const float* __restrict__ b2,
                          float* __restrict__ xhat) {
    extern __shared__ float sm[];
    float* Ts  = sm;               // [64][65]
    float* Zs  = sm + 4160;        // [64][65]
    float* W1s = sm + 8320;        // [64][64]
    float* W2s = sm + 4160;        // [64][128], overlays phase-1 space
    int nb = blockIdx.x * 64;
    int tid = threadIdx.x;
    int tx = tid & 15, ty = tid >> 4;
#pragma unroll
    for (int i = 0; i < 4; i++) {
        int v = tid + i * 256;
        int row = v >> 4, kq = (v & 15) << 2;
        int gr = nb + row;
        float4 zv = make_float4(0.f, 0.f, 0.f, 0.f);
        if (gr < NN) zv = *(const float4*)(z + (size_t)gr * CC + kq);
        Zs[row * 65 + kq + 0] = zv.x; Zs[row * 65 + kq + 1] = zv.y;
        Zs[row * 65 + kq + 2] = zv.z; Zs[row * 65 + kq + 3] = zv.w;
        *(float4*)&W1s[row * 64 + kq] = *(const float4*)(w1 + row * CC + kq);
    }
    __syncthreads();
    {
        float acc[4][4];
#pragma unroll
        for (int j = 0; j < 4; j++) {
            float bv = b1[tx * 4 + j];
#pragma unroll
            for (int i = 0; i < 4; i++) acc[i][j] = bv;
        }
#pragma unroll 16
        for (int k = 0; k < 64; k++) {
            float a0 = Zs[(ty * 4 + 0) * 65 + k];
            float a1 = Zs[(ty * 4 + 1) * 65 + k];
            float a2 = Zs[(ty * 4 + 2) * 65 + k];
            float a3 = Zs[(ty * 4 + 3) * 65 + k];
            float4 b = *(float4*)&W1s[k * 64 + tx * 4];
            acc[0][0] += a0 * b.x; acc[0][1] += a0 * b.y; acc[0][2] += a0 * b.z; acc[0][3] += a0 * b.w;
            acc[1][0] += a1 * b.x; acc[1][1] += a1 * b.y; acc[1][2] += a1 * b.z; acc[1][3] += a1 * b.w;
            acc[2][0] += a2 * b.x; acc[2][1] += a2 * b.y; acc[2][2] += a2 * b.z; acc[2][3] += a2 * b.w;
            acc[3][0] += a3 * b.x; acc[3][1] += a3 * b.y; acc[3][2] += a3 * b.z; acc[3][3] += a3 * b.w;
        }
#pragma unroll
        for (int i = 0; i < 4; i++)
#pragma unroll
            for (int j = 0; j < 4; j++)
                Ts[(ty * 4 + i) * 65 + tx * 4 + j] = elu1(acc[i][j]);
    }
    __syncthreads();
#pragma unroll
    for (int i = 0; i < 8; i++) {
        int v = tid + i * 256;
        int k = v >> 5, cq = (v & 31) << 2;
        *(float4*)&W2s[k * 128 + cq] = *(const float4*)(w2 + k * FIN + cq);
    }
    __syncthreads();
    {
        float acc[4][8];
#pragma unroll
        for (int j = 0; j < 4; j++) {
            float bva = b2[tx * 4 + j], bvb = b2[64 + tx * 4 + j];
#pragma unroll
            for (int i = 0; i < 4; i++) { acc[i][j] = bva; acc[i][j + 4] = bvb; }
        }
#pragma unroll 8
        for (int k = 0; k < 64; k++) {
            float a0 = Ts[(ty * 4 + 0) * 65 + k];
            float a1 = Ts[(ty * 4 + 1) * 65 + k];
            float a2 = Ts[(ty * 4 + 2) * 65 + k];
            float a3 = Ts[(ty * 4 + 3) * 65 + k];
            float4 ba = *(float4*)&W2s[k * 128 + tx * 4];
            float4 bb = *(float4*)&W2s[k * 128 + 64 + tx * 4];
            acc[0][0] += a0 * ba.x; acc[0][1] += a0 * ba.y; acc[0][2] += a0 * ba.z; acc[0][3] += a0 * ba.w;
            acc[1][0] += a1 * ba.x; acc[1][1] += a1 * ba.y; acc[1][2] += a1 * ba.z; acc[1][3] += a1 * ba.w;
            acc[2][0] += a2 * ba.x; acc[2][1] += a2 * ba.y; acc[2][2] += a2 * ba.z; acc[2][3] += a2 * ba.w;
            acc[3][0] += a3 * ba.x; acc[3][1] += a3 * ba.y; acc[3][2] += a3 * ba.z; acc[3][3] += a3 * ba.w;
            acc[0][4] += a0 * bb.x; acc[0][5] += a0 * bb.y; acc[0][6] += a0 * bb.z; acc[0][7] += a0 * bb.w;
            acc[1][4] += a1 * bb.x; acc[1][5] += a1 * bb.y; acc[1][6] += a1 * bb.z; acc[1][7] += a1 * bb.w;
            acc[2][4] += a2 * bb.x; acc[2][5] += a2 * bb.y; acc[2][6] += a2 * bb.z; acc[2][7] += a2 * bb.w;
            acc[3][4] += a3 * bb.x; acc[3][5] += a3 * bb.y; acc[3][6] += a3 * bb.z; acc[3][7] += a3 * bb.w;
        }
#pragma unroll
        for (int i = 0; i < 4; i++) {
            int gr = nb + ty * 4 + i;
            if (gr < NN) {
                *(float4*)(xhat + (size_t)gr * FIN + tx * 4) =
                    make_float4(acc[i][0], acc[i][1], acc[i][2], acc[i][3]);
                *(float4*)(xhat + (size_t)gr * FIN + 64 + tx * 4) =
                    make_float4(acc[i][4], acc[i][5], acc[i][6], acc[i][7]);
            }
        }
    }
}

// ---------------- host (stream-forked CSR build) ----------------
extern "C" void kernel_launch(void* const* d_in, const int* in_sizes, int n_in,
                              void* d_out, int out_size) {
    const float* x      = (const float*)d_in[0];
    const int*   ei     = (const int*)  d_in[1];   // [M,2,E]
    const float* eattr  = (const float*)d_in[2];   // [M,E,1]
    const float* lin1w  = (const float*)d_in[3];
    const float* a1s    = (const float*)d_in[4];
    const float* a1d    = (const float*)d_in[5];
    const float* l1e    = (const float*)d_in[6];
    const float* a1e    = (const float*)d_in[7];
    const float* b1     = (const float*)d_in[8];
    const float* bn1g   = (const float*)d_in[9];
    const float* bn1b   = (const float*)d_in[10];
    const float* sem1w  = (const float*)d_in[11];
    const float* sem1b  = (const float*)d_in[12];
    const float* sem1v  = (const float*)d_in[13];
    const float* lin2w  = (const float*)d_in[14];
    const float* a2s    = (const float*)d_in[15];
    const float* a2d    = (const float*)d_in[16];
    const float* l2e    = (const float*)d_in[17];
    const float* a2e    = (const float*)d_in[18];
    const float* b2     = (const float*)d_in[19];
    const float* bn2g   = (const float*)d_in[20];
    const float* bn2b   = (const float*)d_in[21];
    const float* sem2w  = (const float*)d_in[22];
    const float* sem2b  = (const float*)d_in[23];
    const float* sem2v  = (const float*)d_in[24];
    const float* dec1w  = (const float*)d_in[25];
    const float* dec1b  = (const float*)d_in[26];
    const float* dec2w  = (const float*)d_in[27];
    const float* dec2b  = (const float*)d_in[28];

    float* z_out    = (float*)d_out;             // [N, C2]
    float* xhat     = z_out + NN * CC;           // [N, IN]
    float* beta_out = xhat + NN * FIN;           // [N, M]

    float* houtp = nullptr;
    cudaGetSymbolAddress((void**)&houtp, g_hout);
    float *edot1p = nullptr, *edot2p = nullptr, *aff1p = nullptr, *aff2p = nullptr;
    cudaGetSymbolAddress((void**)&edot1p, g_edot1);
    cudaGetSymbolAddress((void**)&edot2p, g_edot2);
    cudaGetSymbolAddress((void**)&aff1p, g_aff1);
    cudaGetSymbolAddress((void**)&aff2p, g_aff2);

    const int EB = (EE + 255) / 256;
    const int NB64 = (NN + 63) / 64;
    const int NB128 = (NN + 127) / 128;

    int smem2 = (64 * 68 + 64 * 64) * 4;    // 33792

    static cudaStream_t s2;
    static cudaEvent_t evA, evB;
    static bool init_done = false;
    if (!init_done) {
        cudaFuncSetAttribute(k_sgemm<CC, CC, 64, 1>, cudaFuncAttributeMaxDynamicSharedMemorySize, smem2);
        cudaFuncSetAttribute(k_decoder, cudaFuncAttributeMaxDynamicSharedMemorySize, 12416 * 4);
        cudaStreamCreateWithFlags(&s2, cudaStreamNonBlocking);
        cudaEventCreateWithFlags(&evA, cudaEventDisableTiming);
        cudaEventCreateWithFlags(&evB, cudaEventDisableTiming);
        init_done = true;
    }

    // ---- fork: CSR build + BN on s2, concurrent with sgemm1 on origin stream ----
    cudaEventRecord(evA, 0);
    cudaStreamWaitEvent(s2, evA, 0);
    k_zero1<<<(MM * NN + 255) / 256, 256, 0, s2>>>();
    k_build<<<dim3(EB, MM), 256, 0, s2>>>(ei, eattr);
    k_scan<<<MM, 1024, 0, s2>>>();
    k_scatter<<<dim3(EB, MM), 256, 0, s2>>>(ei);
    k_bnfin<HH, CC><<<1, MM * HH * 32, 0, s2>>>(l1e, a1e, bn1g, bn1b, edot1p, aff1p);
    k_bnfin<1, CC><<<1, MM * 32, 0, s2>>>(l2e, a2e, bn2g, bn2b, edot2p, aff2p);
    cudaEventRecord(evB, s2);

    k_sgemm1<FIN, HH * CC, HH><<<dim3(2, NB128, MM), 256>>>(x, lin1w, a1s, a1d);
    cudaStreamWaitEvent(0, evB, 0);

    // ---- HAN layer 1 (heads = 4) ----
    k_gat4<<<dim3(NN / 8, MM), 256>>>(b1);
    k_semantic<<<(NN + 3) / 4, 256>>>(sem1w, sem1b, sem1v, houtp, nullptr);

    // ---- HAN layer 2 (heads = 1) ----
    k_sgemm<CC, CC, 64, 1><<<dim3(1, NB64, MM), 256, smem2>>>(houtp, lin2w, a2s, a2d);
    k_gat1<<<dim3(NN / 32, MM), 256>>>(b2);
    k_semantic<<<(NN + 3) / 4, 256>>>(sem2w, sem2b, sem2v, z_out, beta_out);

    // ---- decoder ----
    k_decoder<<<NB64, 256, 12416 * 4>>>(z_out, dec1w, dec1b, dec2w, dec2b, xhat);
}